// round 1
// baseline (speedup 1.0000x reference)
#include <cuda_runtime.h>
#include <math.h>

#define NROWS 16384        // B * L = 16 * 1024
#define SEQL  1024
#define NB    16
#define SCALE_INV 0.08838834764831845f   // 1/sqrt(128)

// ---------------- persistent scratch (no runtime alloc allowed) ----------------
__device__ float g_x [NROWS*128];
__device__ float g_y [NROWS*128];
__device__ float g_q [NROWS*128];
__device__ float g_k [NROWS*128];
__device__ float g_xu[NROWS*128];
__device__ float g_yu[NROWS*128];
__device__ float g_vx [NROWS];
__device__ float g_vy [NROWS];
__device__ float g_vxm[NROWS];
__device__ float g_vym[NROWS];

__device__ __forceinline__ float sigmoidf_fast(float x) {
    return __fdividef(1.f, 1.f + __expf(-x));
}

// 64x128 output tile GEMM over K=128.
// As: [64][132] row-major (rows = output rows), Ws: [128][WSTRIDE] (row k, col = output col).
// Thread map: 256 threads, tr = tid>>4 (16), tc = tid&15 (16); micro-tile 4 rows x 8 cols.
template<int WSTRIDE>
__device__ __forceinline__ void gemm_tile(const float* __restrict__ As,
                                          const float* __restrict__ Ws,
                                          int tr, int tc, float acc[4][8]) {
    for (int k = 0; k < 128; k += 4) {
        float a[4][4];
#pragma unroll
        for (int i = 0; i < 4; i++) {
            float4 av = *(const float4*)(As + (tr*4 + i)*132 + k);
            a[i][0] = av.x; a[i][1] = av.y; a[i][2] = av.z; a[i][3] = av.w;
        }
#pragma unroll
        for (int kk = 0; kk < 4; kk++) {
            float4 w0 = *(const float4*)(Ws + (k + kk)*WSTRIDE + tc*8);
            float4 w1 = *(const float4*)(Ws + (k + kk)*WSTRIDE + tc*8 + 4);
#pragma unroll
            for (int i = 0; i < 4; i++) {
                float av = a[i][kk];
                acc[i][0] += av*w0.x; acc[i][1] += av*w0.y;
                acc[i][2] += av*w0.z; acc[i][3] += av*w0.w;
                acc[i][4] += av*w1.x; acc[i][5] += av*w1.y;
                acc[i][6] += av*w1.z; acc[i][7] += av*w1.w;
            }
        }
    }
}

// ---------------- embed: out = relu(A @ W + b), rows = 16384 ----------------
__global__ __launch_bounds__(256) void embed_kernel(
    const float* __restrict__ A, const float* __restrict__ W,
    const float* __restrict__ bias, float* __restrict__ out) {
    extern __shared__ float sm[];
    float* Ws = sm;              // 128*128
    float* As = sm + 16384;      // 64*132
    const int tid  = threadIdx.x;
    const int row0 = blockIdx.x * 64;

    const float4* W4 = (const float4*)W;
    float4* Ws4 = (float4*)Ws;
#pragma unroll
    for (int i = 0; i < 16; i++) Ws4[tid + 256*i] = W4[tid + 256*i];
#pragma unroll
    for (int i = 0; i < 8; i++) {
        int fi = tid + 256*i;
        int r = fi >> 5, c4 = fi & 31;
        *(float4*)(As + r*132 + c4*4) =
            ((const float4*)(A + (size_t)(row0 + r)*128))[c4];
    }
    __syncthreads();

    const int tr = tid >> 4, tc = tid & 15;
    float acc[4][8];
#pragma unroll
    for (int i = 0; i < 4; i++)
#pragma unroll
        for (int j = 0; j < 8; j++) acc[i][j] = 0.f;

    gemm_tile<128>(As, Ws, tr, tc, acc);

    float4 b0 = *(const float4*)(bias + tc*8);
    float4 b1 = *(const float4*)(bias + tc*8 + 4);
#pragma unroll
    for (int i = 0; i < 4; i++) {
        int r = row0 + tr*4 + i;
        float4 o0, o1;
        o0.x = fmaxf(acc[i][0] + b0.x, 0.f);
        o0.y = fmaxf(acc[i][1] + b0.y, 0.f);
        o0.z = fmaxf(acc[i][2] + b0.z, 0.f);
        o0.w = fmaxf(acc[i][3] + b0.w, 0.f);
        o1.x = fmaxf(acc[i][4] + b1.x, 0.f);
        o1.y = fmaxf(acc[i][5] + b1.y, 0.f);
        o1.z = fmaxf(acc[i][6] + b1.z, 0.f);
        o1.w = fmaxf(acc[i][7] + b1.w, 0.f);
        *(float4*)(out + (size_t)r*128 + tc*8)     = o0;
        *(float4*)(out + (size_t)r*128 + tc*8 + 4) = o1;
    }
}

// ---------------- layernorm (in place), one warp per row ----------------
__global__ __launch_bounds__(256) void ln_kernel(
    float* __restrict__ X, const float* __restrict__ g, const float* __restrict__ bb) {
    int row  = blockIdx.x * 8 + (threadIdx.x >> 5);
    int lane = threadIdx.x & 31;
    float4* Xr = (float4*)(X + (size_t)row * 128);
    float4 v = Xr[lane];
    float s = v.x + v.y + v.z + v.w;
#pragma unroll
    for (int o = 16; o; o >>= 1) s += __shfl_xor_sync(0xffffffffu, s, o);
    float m = s * (1.f/128.f);
    float d0 = v.x - m, d1 = v.y - m, d2 = v.z - m, d3 = v.w - m;
    float q = d0*d0 + d1*d1 + d2*d2 + d3*d3;
#pragma unroll
    for (int o = 16; o; o >>= 1) q += __shfl_xor_sync(0xffffffffu, q, o);
    float inv = rsqrtf(q * (1.f/128.f) + 1e-5f);
    float4 gg = ((const float4*)g)[lane];
    float4 bv = ((const float4*)bb)[lane];
    v.x = d0*inv*gg.x + bv.x;
    v.y = d1*inv*gg.y + bv.y;
    v.z = d2*inv*gg.z + bv.z;
    v.w = d3*inv*gg.w + bv.w;
    Xr[lane] = v;
}

// ---------------- projections: Q = X@Wq+bq ; U = relu(X@Wu+bu) ; v = relu(X@wv+bv) ----------------
__global__ __launch_bounds__(256) void proj_kernel(
    const float* __restrict__ X,
    const float* __restrict__ Wq, const float* __restrict__ bq,
    const float* __restrict__ Wu, const float* __restrict__ bu,
    const float* __restrict__ wv, const float* __restrict__ bv,
    const float* __restrict__ mask,
    float* __restrict__ Q, float* __restrict__ U,
    float* __restrict__ Vs, float* __restrict__ Vsm) {
    extern __shared__ float sm[];
    float* Ws1 = sm;              // 16384
    float* Ws2 = sm + 16384;      // 16384
    float* As  = sm + 32768;      // 64*132
    float* wvs = As + 64*132;     // 128
    const int tid  = threadIdx.x;
    const int row0 = blockIdx.x * 64;

    const float4* Wq4 = (const float4*)Wq;
    const float4* Wu4 = (const float4*)Wu;
    float4* Ws14 = (float4*)Ws1;
    float4* Ws24 = (float4*)Ws2;
#pragma unroll
    for (int i = 0; i < 16; i++) {
        Ws14[tid + 256*i] = Wq4[tid + 256*i];
        Ws24[tid + 256*i] = Wu4[tid + 256*i];
    }
    if (tid < 32) ((float4*)wvs)[tid] = ((const float4*)wv)[tid];
#pragma unroll
    for (int i = 0; i < 8; i++) {
        int fi = tid + 256*i;
        int r = fi >> 5, c4 = fi & 31;
        *(float4*)(As + r*132 + c4*4) =
            ((const float4*)(X + (size_t)(row0 + r)*128))[c4];
    }
    __syncthreads();

    const int tr = tid >> 4, tc = tid & 15;

    {   // Q (no relu)
        float acc[4][8];
#pragma unroll
        for (int i = 0; i < 4; i++)
#pragma unroll
            for (int j = 0; j < 8; j++) acc[i][j] = 0.f;
        gemm_tile<128>(As, Ws1, tr, tc, acc);
        float4 b0 = *(const float4*)(bq + tc*8);
        float4 b1 = *(const float4*)(bq + tc*8 + 4);
#pragma unroll
        for (int i = 0; i < 4; i++) {
            int r = row0 + tr*4 + i;
            float4 o0, o1;
            o0.x = acc[i][0] + b0.x; o0.y = acc[i][1] + b0.y;
            o0.z = acc[i][2] + b0.z; o0.w = acc[i][3] + b0.w;
            o1.x = acc[i][4] + b1.x; o1.y = acc[i][5] + b1.y;
            o1.z = acc[i][6] + b1.z; o1.w = acc[i][7] + b1.w;
            *(float4*)(Q + (size_t)r*128 + tc*8)     = o0;
            *(float4*)(Q + (size_t)r*128 + tc*8 + 4) = o1;
        }
    }
    {   // U (relu)
        float acc[4][8];
#pragma unroll
        for (int i = 0; i < 4; i++)
#pragma unroll
            for (int j = 0; j < 8; j++) acc[i][j] = 0.f;
        gemm_tile<128>(As, Ws2, tr, tc, acc);
        float4 b0 = *(const float4*)(bu + tc*8);
        float4 b1 = *(const float4*)(bu + tc*8 + 4);
#pragma unroll
        for (int i = 0; i < 4; i++) {
            int r = row0 + tr*4 + i;
            float4 o0, o1;
            o0.x = fmaxf(acc[i][0] + b0.x, 0.f);
            o0.y = fmaxf(acc[i][1] + b0.y, 0.f);
            o0.z = fmaxf(acc[i][2] + b0.z, 0.f);
            o0.w = fmaxf(acc[i][3] + b0.w, 0.f);
            o1.x = fmaxf(acc[i][4] + b1.x, 0.f);
            o1.y = fmaxf(acc[i][5] + b1.y, 0.f);
            o1.z = fmaxf(acc[i][6] + b1.z, 0.f);
            o1.w = fmaxf(acc[i][7] + b1.w, 0.f);
            *(float4*)(U + (size_t)r*128 + tc*8)     = o0;
            *(float4*)(U + (size_t)r*128 + tc*8 + 4) = o1;
        }
    }
    // gating scalar per row
    if (tid < 64) {
        float s = 0.f;
        for (int k2 = 0; k2 < 128; k2++) s += As[tid*132 + k2] * wvs[k2];
        float v = fmaxf(s + bv[0], 0.f);
        int gr = row0 + tid;
        Vs[gr]  = v;
        Vsm[gr] = v * mask[gr];
    }
}

// ---------------- fused interaction pass ----------------
// Out_r += aS_r * sum_c sigmoid((A_r . B_c) * SCALE_INV) * bS_c * U_c
// Pass1: A=q, B=k, U=y_upd, aS=vx*mask1, bS=vy, Out=x
// Pass2: A=k, B=q, U=x_upd, aS=vy*mask2, bS=vx, Out=y
__global__ __launch_bounds__(256) void interact_kernel(
    const float* __restrict__ A,  const float* __restrict__ Bm,
    const float* __restrict__ U,  const float* __restrict__ aS,
    const float* __restrict__ bS, float* __restrict__ Out) {
    extern __shared__ float sm[];
    float* Aq  = sm;                     // 64*132  = 8448
    float* Kt  = sm + 8448;              // 128*132 = 16896 (transposed B tile: [k][j])
    float* Us  = Kt + 16896;             // 128*132 = 16896
    float* Ss  = Us + 16896;             // 64*132  = 8448
    float* bSs = Ss + 8448;              // 128
    float* aSs = bSs + 128;              // 64
    const int tid = threadIdx.x;
    const int b   = blockIdx.y;
    const int i0  = blockIdx.x * 64;
    const int tr  = tid >> 4, tc = tid & 15;

    const float* Ab = A + ((size_t)b*SEQL + i0)*128;
#pragma unroll
    for (int i = 0; i < 8; i++) {
        int fi = tid + 256*i;
        int r = fi >> 5, c4 = fi & 31;
        *(float4*)(Aq + r*132 + c4*4) = ((const float4*)(Ab + r*128))[c4];
    }
    if (tid < 64) aSs[tid] = aS[b*SEQL + i0 + tid];

    float acc[4][8];
#pragma unroll
    for (int i = 0; i < 4; i++)
#pragma unroll
        for (int j = 0; j < 8; j++) acc[i][j] = 0.f;

    for (int jt = 0; jt < 8; jt++) {
        const int j0 = jt * 128;
        __syncthreads();   // previous tile fully consumed (also covers Aq/aSs on jt==0)

        // load B tile transposed: Kt[k][j]. Lane j = tid&127 -> STS conflict-free.
        const float* Kb = Bm + ((size_t)b*SEQL + j0)*128;
        {
            int j  = tid & 127;
            int hi = tid >> 7;
#pragma unroll
            for (int i = 0; i < 16; i++) {
                int c4 = 2*i + hi;
                float4 v = ((const float4*)(Kb + j*128))[c4];
                Kt[(c4*4 + 0)*132 + j] = v.x;
                Kt[(c4*4 + 1)*132 + j] = v.y;
                Kt[(c4*4 + 2)*132 + j] = v.z;
                Kt[(c4*4 + 3)*132 + j] = v.w;
            }
        }
        const float* Ub = U + ((size_t)b*SEQL + j0)*128;
#pragma unroll
        for (int i = 0; i < 16; i++) {
            int fi = tid + 256*i;
            int r = fi >> 5, c4 = fi & 31;
            *(float4*)(Us + r*132 + c4*4) = ((const float4*)(Ub + r*128))[c4];
        }
        if (tid < 128) bSs[tid] = bS[b*SEQL + j0 + tid];
        __syncthreads();

        // S = Aq @ Kt  (64 x 128 over K=128)
        float sacc[4][8];
#pragma unroll
        for (int i = 0; i < 4; i++)
#pragma unroll
            for (int j = 0; j < 8; j++) sacc[i][j] = 0.f;
        gemm_tile<132>(Aq, Kt, tr, tc, sacc);

        // transform: sigmoid(S/scale) * bS_col, spill to smem
        float bv[8];
#pragma unroll
        for (int j = 0; j < 8; j++) bv[j] = bSs[tc*8 + j];
#pragma unroll
        for (int i = 0; i < 4; i++) {
            float4 s0, s1;
            s0.x = sigmoidf_fast(sacc[i][0]*SCALE_INV) * bv[0];
            s0.y = sigmoidf_fast(sacc[i][1]*SCALE_INV) * bv[1];
            s0.z = sigmoidf_fast(sacc[i][2]*SCALE_INV) * bv[2];
            s0.w = sigmoidf_fast(sacc[i][3]*SCALE_INV) * bv[3];
            s1.x = sigmoidf_fast(sacc[i][4]*SCALE_INV) * bv[4];
            s1.y = sigmoidf_fast(sacc[i][5]*SCALE_INV) * bv[5];
            s1.z = sigmoidf_fast(sacc[i][6]*SCALE_INV) * bv[6];
            s1.w = sigmoidf_fast(sacc[i][7]*SCALE_INV) * bv[7];
            *(float4*)(Ss + (tr*4 + i)*132 + tc*8)     = s0;
            *(float4*)(Ss + (tr*4 + i)*132 + tc*8 + 4) = s1;
        }
        __syncthreads();

        // acc += Ss @ Us  (64 x 128 over K=128)
        gemm_tile<132>(Ss, Us, tr, tc, acc);
    }

    // residual accumulate into Out (Out already holds post-LN x or y)
    float* Ob = Out + ((size_t)b*SEQL + i0)*128;
#pragma unroll
    for (int i = 0; i < 4; i++) {
        int r = tr*4 + i;
        float av = aSs[r];
        float4 o0 = *(const float4*)(Ob + r*128 + tc*8);
        float4 o1 = *(const float4*)(Ob + r*128 + tc*8 + 4);
        o0.x += av*acc[i][0]; o0.y += av*acc[i][1];
        o0.z += av*acc[i][2]; o0.w += av*acc[i][3];
        o1.x += av*acc[i][4]; o1.y += av*acc[i][5];
        o1.z += av*acc[i][6]; o1.w += av*acc[i][7];
        *(float4*)(Ob + r*128 + tc*8)     = o0;
        *(float4*)(Ob + r*128 + tc*8 + 4) = o1;
    }
}

// ---------------- pooling + head, one CTA per batch ----------------
__device__ __forceinline__ float blk_reduce(float v, float* red, bool ismax) {
#pragma unroll
    for (int o = 16; o; o >>= 1) {
        float t = __shfl_xor_sync(0xffffffffu, v, o);
        v = ismax ? fmaxf(v, t) : v + t;
    }
    if ((threadIdx.x & 31) == 0) red[threadIdx.x >> 5] = v;
    __syncthreads();
    float r = red[0];
#pragma unroll
    for (int i = 1; i < 8; i++) r = ismax ? fmaxf(r, red[i]) : r + red[i];
    __syncthreads();
    return r;
}

__global__ __launch_bounds__(256) void pool_head_kernel(
    const float* __restrict__ Xg, const float* __restrict__ Yg,
    const float* __restrict__ fc_w, const float* __restrict__ fc_b,
    const float* __restrict__ out_w, const float* __restrict__ out_b,
    float* __restrict__ out) {
    __shared__ float w[1024];
    __shared__ float red[8];
    __shared__ float pp[256];
    __shared__ float xp[128];
    __shared__ float yp[128];
    const int tid = threadIdx.x;
    const int b   = blockIdx.x;

    for (int s = 0; s < 2; s++) {
        const float* S = (s ? Yg : Xg) + (size_t)b * SEQL * 128;
        float* dst = s ? yp : xp;
        for (int l = tid; l < SEQL; l += 256) {
            const float4* row = (const float4*)(S + (size_t)l*128);
            float acc = 0.f;
#pragma unroll
            for (int c = 0; c < 32; c++) {
                float4 v = row[c];
                acc += v.x*v.x + v.y*v.y + v.z*v.z + v.w*v.w;
            }
            w[l] = sqrtf(acc);
        }
        __syncthreads();
        float lm = -1e30f;
        for (int l = tid; l < SEQL; l += 256) lm = fmaxf(lm, w[l]);
        float mx = blk_reduce(lm, red, true);
        float ls = 0.f;
        for (int l = tid; l < SEQL; l += 256) { float e = expf(w[l] - mx); w[l] = e; ls += e; }
        float tot = blk_reduce(ls, red, false);
        float inv = 1.f / tot;

        int d = tid & 127, half = tid >> 7;
        float p = 0.f;
        for (int l = half; l < SEQL; l += 2) p += S[(size_t)l*128 + d] * w[l];
        pp[half*128 + d] = p;
        __syncthreads();
        if (tid < 128) dst[tid] = (pp[tid] + pp[128 + tid]) * inv;
        __syncthreads();
    }

    float h = 0.f;
    if (tid < 128) {
        h = fc_b[tid];
        for (int k2 = 0; k2 < 128; k2++) h += xp[k2] * fc_w[k2*128 + tid];
        for (int k2 = 0; k2 < 128; k2++) h += yp[k2] * fc_w[(128 + k2)*128 + tid];
        h = fmaxf(h, 0.f) * out_w[tid];
    }
    float tot = blk_reduce(h, red, false);
    if (tid == 0) out[b] = 1.f / (1.f + expf(-(tot + out_b[0])));
}

// ---------------- launch ----------------
extern "C" void kernel_launch(void* const* d_in, const int* in_sizes, int n_in,
                              void* d_out, int out_size) {
    (void)in_sizes; (void)n_in; (void)out_size;
    const float* seq1  = (const float*)d_in[0];
    const float* seq2  = (const float*)d_in[1];
    const float* mask1 = (const float*)d_in[2];
    const float* mask2 = (const float*)d_in[3];
    const float* l1_w  = (const float*)d_in[4];
    const float* l1_b  = (const float*)d_in[5];
    const float* l2_w  = (const float*)d_in[6];
    const float* l2_b  = (const float*)d_in[7];
    const float* ln1_g = (const float*)d_in[8];
    const float* ln1_b = (const float*)d_in[9];
    const float* ln2_g = (const float*)d_in[10];
    const float* ln2_b = (const float*)d_in[11];
    const float* wq_w  = (const float*)d_in[12];
    const float* wq_b  = (const float*)d_in[13];
    const float* wk_w  = (const float*)d_in[14];
    const float* wk_b  = (const float*)d_in[15];
    const float* wvx_w = (const float*)d_in[16];
    const float* wvx_b = (const float*)d_in[17];
    const float* wvy_w = (const float*)d_in[18];
    const float* wvy_b = (const float*)d_in[19];
    const float* wx_w  = (const float*)d_in[20];
    const float* wx_b  = (const float*)d_in[21];
    const float* wy_w  = (const float*)d_in[22];
    const float* wy_b  = (const float*)d_in[23];
    const float* fc_w  = (const float*)d_in[24];
    const float* fc_b  = (const float*)d_in[25];
    const float* out_w = (const float*)d_in[26];
    const float* out_b = (const float*)d_in[27];

    float *x, *y, *q, *k, *xu, *yu, *vx, *vy, *vxm, *vym;
    cudaGetSymbolAddress((void**)&x,  g_x);
    cudaGetSymbolAddress((void**)&y,  g_y);
    cudaGetSymbolAddress((void**)&q,  g_q);
    cudaGetSymbolAddress((void**)&k,  g_k);
    cudaGetSymbolAddress((void**)&xu, g_xu);
    cudaGetSymbolAddress((void**)&yu, g_yu);
    cudaGetSymbolAddress((void**)&vx, g_vx);
    cudaGetSymbolAddress((void**)&vy, g_vy);
    cudaGetSymbolAddress((void**)&vxm, g_vxm);
    cudaGetSymbolAddress((void**)&vym, g_vym);

    const int EMB_SMEM  = (16384 + 64*132) * 4;                           // 99328
    const int PROJ_SMEM = (2*16384 + 64*132 + 128) * 4;                   // 165376
    const int INT_SMEM  = (64*132 + 128*132 + 128*132 + 64*132 + 192)*4;  // 203520

    cudaFuncSetAttribute(embed_kernel,    cudaFuncAttributeMaxDynamicSharedMemorySize, EMB_SMEM);
    cudaFuncSetAttribute(proj_kernel,     cudaFuncAttributeMaxDynamicSharedMemorySize, PROJ_SMEM);
    cudaFuncSetAttribute(interact_kernel, cudaFuncAttributeMaxDynamicSharedMemorySize, INT_SMEM);

    embed_kernel<<<256, 256, EMB_SMEM>>>(seq1, l1_w, l1_b, x);
    embed_kernel<<<256, 256, EMB_SMEM>>>(seq2, l2_w, l2_b, y);

    for (int i = 0; i < 3; i++) {
        ln_kernel<<<2048, 256>>>(x, ln1_g + i*128, ln1_b + i*128);
        ln_kernel<<<2048, 256>>>(y, ln2_g + i*128, ln2_b + i*128);
        proj_kernel<<<256, 256, PROJ_SMEM>>>(x, wq_w + i*16384, wq_b + i*128,
                                             wx_w + i*16384, wx_b + i*128,
                                             wvx_w + i*128, wvx_b + i, mask1,
                                             q, xu, vx, vxm);
        proj_kernel<<<256, 256, PROJ_SMEM>>>(y, wk_w + i*16384, wk_b + i*128,
                                             wy_w + i*16384, wy_b + i*128,
                                             wvy_w + i*128, wvy_b + i, mask2,
                                             k, yu, vy, vym);
        dim3 ig(16, 16);
        interact_kernel<<<ig, 256, INT_SMEM>>>(q, k, yu, vxm, vy, x);
        interact_kernel<<<ig, 256, INT_SMEM>>>(k, q, xu, vym, vx, y);
    }
    pool_head_kernel<<<16, 256>>>(x, y, fc_w, fc_b, out_w, out_b, (float*)d_out);
}

// round 4
// speedup vs baseline: 2.3621x; 2.3621x over previous
#include <cuda_runtime.h>
#include <cuda_bf16.h>
#include <cstdint>
#include <math.h>

#define NROWS 16384        // B * L = 16 * 1024
#define SEQL  1024
#define SCALE_INV 0.08838834764831845f   // 1/sqrt(128)

// ---------------- persistent scratch (no runtime alloc allowed) ----------------
__device__ float g_x [NROWS*128];
__device__ float g_y [NROWS*128];
__device__ float g_q [NROWS*128];
__device__ float g_k [NROWS*128];
__device__ float g_xu[NROWS*128];
__device__ float g_yu[NROWS*128];
__device__ float g_vx [NROWS];
__device__ float g_vy [NROWS];
__device__ float g_vxm[NROWS];
__device__ float g_vym[NROWS];

__device__ __forceinline__ float sigmoidf_fast(float x) {
    return __fdividef(1.f, 1.f + __expf(-x));
}

__device__ __forceinline__ uint32_t smem_u32(const void* p) {
    uint32_t a;
    asm("{ .reg .u64 t; cvta.to.shared.u64 t, %1; cvt.u32.u64 %0, t; }" : "=r"(a) : "l"(p));
    return a;
}

__device__ __forceinline__ uint32_t packbf(__nv_bfloat16 a, __nv_bfloat16 b) {
    __nv_bfloat162 t(a, b);
    return *reinterpret_cast<uint32_t*>(&t);
}

__device__ __forceinline__ void ldsm_x4(uint32_t r[4], uint32_t addr) {
    asm volatile("ldmatrix.sync.aligned.m8n8.x4.shared.b16 {%0,%1,%2,%3}, [%4];"
                 : "=r"(r[0]), "=r"(r[1]), "=r"(r[2]), "=r"(r[3]) : "r"(addr));
}
__device__ __forceinline__ void ldsm_x4t(uint32_t r[4], uint32_t addr) {
    asm volatile("ldmatrix.sync.aligned.m8n8.x4.trans.shared.b16 {%0,%1,%2,%3}, [%4];"
                 : "=r"(r[0]), "=r"(r[1]), "=r"(r[2]), "=r"(r[3]) : "r"(addr));
}
__device__ __forceinline__ void mma_bf16(float c[4], const uint32_t a[4],
                                         uint32_t b0, uint32_t b1) {
    asm volatile(
        "mma.sync.aligned.m16n8k16.row.col.f32.bf16.bf16.f32 "
        "{%0,%1,%2,%3}, {%4,%5,%6,%7}, {%8,%9}, {%0,%1,%2,%3};"
        : "+f"(c[0]), "+f"(c[1]), "+f"(c[2]), "+f"(c[3])
        : "r"(a[0]), "r"(a[1]), "r"(a[2]), "r"(a[3]), "r"(b0), "r"(b1));
}

// SMEM layout for interact (bytes). bf16 tiles, 128 rows, row stride 272 bytes
// (128 bf16 + 8 pad -> conflict-free ldmatrix: stride mod 128B = 16B shifts banks).
#define IROWB 272
#define ITILE (128 * IROWB)      // 34816
#define O_QH  0
#define O_QL  (O_QH + ITILE)
#define O_KH  (O_QL + ITILE)
#define O_KL  (O_KH + ITILE)
#define O_UH  (O_KL + ITILE)
#define O_UL  (O_UH + ITILE)
#define O_AS  (O_UH + 2*ITILE)   // 128 floats
#define O_BS  (O_AS + 512)       // 128 floats
#define I_SMEM (O_BS + 512)      // 209920 bytes

// Out_i += aS_i * sum_j sigmoid((A_i . B_j)/sqrt(D)) * bS_j * U_j
// A: [B*L,128] "q", B: "k", U update vectors. Per CTA: 128 i-rows; 8 warps x 16 rows.
__global__ __launch_bounds__(256) void interact_mma_kernel(
    const float* __restrict__ A,  const float* __restrict__ Bm,
    const float* __restrict__ U,  const float* __restrict__ aS,
    const float* __restrict__ bS, float* __restrict__ Out) {
    extern __shared__ __align__(16) char sm[];
    const int tid  = threadIdx.x;
    const int w    = tid >> 5, lane = tid & 31;
    const int b    = blockIdx.y;
    const int i0   = blockIdx.x * 128;
    float* aSs = (float*)(sm + O_AS);
    float* bSs = (float*)(sm + O_BS);
    const uint32_t sb = smem_u32(sm);

    // convert Q tile (128 x 128 fp32) -> bf16 hi/lo in smem
    const float* Ab = A + ((size_t)(b * SEQL + i0)) * 128;
    for (int idx = tid; idx < 128 * 64; idx += 256) {
        int r = idx >> 6, cp = idx & 63;
        float2 v = *(const float2*)(Ab + r * 128 + cp * 2);
        __nv_bfloat16 h0 = __float2bfloat16_rn(v.x), h1 = __float2bfloat16_rn(v.y);
        float l0 = v.x - __bfloat162float(h0), l1 = v.y - __bfloat162float(h1);
        uint32_t off = (uint32_t)(r * IROWB + cp * 4);
        *(uint32_t*)(sm + O_QH + off) = packbf(h0, h1);
        *(uint32_t*)(sm + O_QL + off) = packbf(__float2bfloat16_rn(l0), __float2bfloat16_rn(l1));
    }
    if (tid < 128) aSs[tid] = aS[b * SEQL + i0 + tid];

    float oacc[16][4];
#pragma unroll
    for (int n = 0; n < 16; n++)
#pragma unroll
        for (int c = 0; c < 4; c++) oacc[n][c] = 0.f;

    // ldmatrix address components (per lane)
    const uint32_t a_row = 16 * w + (lane & 15);
    const uint32_t a_cadd = (lane & 16) ? 16 : 0;             // +8 cols -> +16 bytes
    const uint32_t b_rsub = (uint32_t)(((lane & 16) ? 8 : 0) + (lane & 7));
    const uint32_t b_cadd = (lane & 8) ? 16 : 0;              // +8 cols -> +16 bytes
    const uint32_t u_radd = (uint32_t)(lane & 15);
    const uint32_t u_cadd = (lane & 16) ? 16 : 0;

    for (int jt = 0; jt < 8; jt++) {
        __syncthreads();   // previous iteration's reads of K/U done
        // K tile (128 x 128) -> bf16 hi/lo
        const float* Kb = Bm + ((size_t)(b * SEQL + jt * 128)) * 128;
        const float* Ub = U  + ((size_t)(b * SEQL + jt * 128)) * 128;
        for (int idx = tid; idx < 128 * 64; idx += 256) {
            int r = idx >> 6, cp = idx & 63;
            uint32_t off = (uint32_t)(r * IROWB + cp * 4);
            float2 v = *(const float2*)(Kb + r * 128 + cp * 2);
            __nv_bfloat16 h0 = __float2bfloat16_rn(v.x), h1 = __float2bfloat16_rn(v.y);
            float l0 = v.x - __bfloat162float(h0), l1 = v.y - __bfloat162float(h1);
            *(uint32_t*)(sm + O_KH + off) = packbf(h0, h1);
            *(uint32_t*)(sm + O_KL + off) = packbf(__float2bfloat16_rn(l0), __float2bfloat16_rn(l1));
            float2 u = *(const float2*)(Ub + r * 128 + cp * 2);
            __nv_bfloat16 g0 = __float2bfloat16_rn(u.x), g1 = __float2bfloat16_rn(u.y);
            float m0 = u.x - __bfloat162float(g0), m1 = u.y - __bfloat162float(g1);
            *(uint32_t*)(sm + O_UH + off) = packbf(g0, g1);
            *(uint32_t*)(sm + O_UL + off) = packbf(__float2bfloat16_rn(m0), __float2bfloat16_rn(m1));
        }
        if (tid < 128) bSs[tid] = bS[b * SEQL + jt * 128 + tid];
        __syncthreads();

        // ---- GEMM1: S[16 x 128] = Q_w @ K^T over d=128 ----
        float sacc[16][4];
#pragma unroll
        for (int n = 0; n < 16; n++)
#pragma unroll
            for (int c = 0; c < 4; c++) sacc[n][c] = 0.f;

#pragma unroll
        for (int kt = 0; kt < 8; kt++) {
            uint32_t aoff = a_row * IROWB + kt * 32 + a_cadd;
            uint32_t ah[4], al[4];
            ldsm_x4(ah, sb + O_QH + aoff);
            ldsm_x4(al, sb + O_QL + aoff);
#pragma unroll
            for (int np = 0; np < 8; np++) {
                uint32_t boff = (16 * np + b_rsub) * IROWB + kt * 32 + b_cadd;
                uint32_t bh[4], bl[4];
                ldsm_x4(bh, sb + O_KH + boff);
                ldsm_x4(bl, sb + O_KL + boff);
                mma_bf16(sacc[2*np],   ah, bh[0], bh[1]);
                mma_bf16(sacc[2*np],   ah, bl[0], bl[1]);
                mma_bf16(sacc[2*np],   al, bh[0], bh[1]);
                mma_bf16(sacc[2*np+1], ah, bh[2], bh[3]);
                mma_bf16(sacc[2*np+1], ah, bl[2], bl[3]);
                mma_bf16(sacc[2*np+1], al, bh[2], bh[3]);
            }
        }

        // ---- epilogue: P = sigmoid(S/sqrt(D)) * bS_j, split hi/lo, keep in regs ----
        uint32_t ph[16][2], pl[16][2];
#pragma unroll
        for (int n = 0; n < 16; n++) {
            int j0 = 8 * n + 2 * (lane & 3);
            float2 bv = *(const float2*)(bSs + j0);
            float p00 = sigmoidf_fast(sacc[n][0] * SCALE_INV) * bv.x;
            float p01 = sigmoidf_fast(sacc[n][1] * SCALE_INV) * bv.y;
            float p10 = sigmoidf_fast(sacc[n][2] * SCALE_INV) * bv.x;
            float p11 = sigmoidf_fast(sacc[n][3] * SCALE_INV) * bv.y;
            __nv_bfloat16 h00 = __float2bfloat16_rn(p00), h01 = __float2bfloat16_rn(p01);
            __nv_bfloat16 h10 = __float2bfloat16_rn(p10), h11 = __float2bfloat16_rn(p11);
            ph[n][0] = packbf(h00, h01);
            ph[n][1] = packbf(h10, h11);
            pl[n][0] = packbf(__float2bfloat16_rn(p00 - __bfloat162float(h00)),
                              __float2bfloat16_rn(p01 - __bfloat162float(h01)));
            pl[n][1] = packbf(__float2bfloat16_rn(p10 - __bfloat162float(h10)),
                              __float2bfloat16_rn(p11 - __bfloat162float(h11)));
        }

        // ---- GEMM2: O[16 x 128] += P @ U over j=128 (U via ldmatrix.trans) ----
#pragma unroll
        for (int kt = 0; kt < 8; kt++) {
            uint32_t ah[4] = { ph[2*kt][0], ph[2*kt][1], ph[2*kt+1][0], ph[2*kt+1][1] };
            uint32_t al[4] = { pl[2*kt][0], pl[2*kt][1], pl[2*kt+1][0], pl[2*kt+1][1] };
#pragma unroll
            for (int np = 0; np < 8; np++) {
                uint32_t uoff = (16 * kt + u_radd) * IROWB + np * 32 + u_cadd;
                uint32_t uh[4], ul[4];
                ldsm_x4t(uh, sb + O_UH + uoff);
                ldsm_x4t(ul, sb + O_UL + uoff);
                mma_bf16(oacc[2*np],   ah, uh[0], uh[1]);
                mma_bf16(oacc[2*np],   ah, ul[0], ul[1]);
                mma_bf16(oacc[2*np],   al, uh[0], uh[1]);
                mma_bf16(oacc[2*np+1], ah, uh[2], uh[3]);
                mma_bf16(oacc[2*np+1], ah, ul[2], ul[3]);
                mma_bf16(oacc[2*np+1], al, uh[2], uh[3]);
            }
        }
    }

    // ---- writeback: Out[i][d] += aS[i] * O[i][d] ----
    {
        int r0 = 16 * w + (lane >> 2), r1 = r0 + 8;
        float av0 = aSs[r0], av1 = aSs[r1];
        float* Ob = Out + ((size_t)(b * SEQL + i0)) * 128;
#pragma unroll
        for (int n = 0; n < 16; n++) {
            int d = 8 * n + 2 * (lane & 3);
            float2 o0 = *(float2*)(Ob + (size_t)r0 * 128 + d);
            o0.x += av0 * oacc[n][0];
            o0.y += av0 * oacc[n][1];
            *(float2*)(Ob + (size_t)r0 * 128 + d) = o0;
            float2 o1 = *(float2*)(Ob + (size_t)r1 * 128 + d);
            o1.x += av1 * oacc[n][2];
            o1.y += av1 * oacc[n][3];
            *(float2*)(Ob + (size_t)r1 * 128 + d) = o1;
        }
    }
}

// ================= SIMT kernels (unchanged from round 1, known-good) =================

template<int WSTRIDE>
__device__ __forceinline__ void gemm_tile(const float* __restrict__ As,
                                          const float* __restrict__ Ws,
                                          int tr, int tc, float acc[4][8]) {
    for (int k = 0; k < 128; k += 4) {
        float a[4][4];
#pragma unroll
        for (int i = 0; i < 4; i++) {
            float4 av = *(const float4*)(As + (tr*4 + i)*132 + k);
            a[i][0] = av.x; a[i][1] = av.y; a[i][2] = av.z; a[i][3] = av.w;
        }
#pragma unroll
        for (int kk = 0; kk < 4; kk++) {
            float4 w0 = *(const float4*)(Ws + (k + kk)*WSTRIDE + tc*8);
            float4 w1 = *(const float4*)(Ws + (k + kk)*WSTRIDE + tc*8 + 4);
#pragma unroll
            for (int i = 0; i < 4; i++) {
                float av = a[i][kk];
                acc[i][0] += av*w0.x; acc[i][1] += av*w0.y;
                acc[i][2] += av*w0.z; acc[i][3] += av*w0.w;
                acc[i][4] += av*w1.x; acc[i][5] += av*w1.y;
                acc[i][6] += av*w1.z; acc[i][7] += av*w1.w;
            }
        }
    }
}

__global__ __launch_bounds__(256) void embed_kernel(
    const float* __restrict__ A, const float* __restrict__ W,
    const float* __restrict__ bias, float* __restrict__ out) {
    extern __shared__ float smf[];
    float* Ws = smf;
    float* As = smf + 16384;
    const int tid  = threadIdx.x;
    const int row0 = blockIdx.x * 64;

    const float4* W4 = (const float4*)W;
    float4* Ws4 = (float4*)Ws;
#pragma unroll
    for (int i = 0; i < 16; i++) Ws4[tid + 256*i] = W4[tid + 256*i];
#pragma unroll
    for (int i = 0; i < 8; i++) {
        int fi = tid + 256*i;
        int r = fi >> 5, c4 = fi & 31;
        *(float4*)(As + r*132 + c4*4) =
            ((const float4*)(A + (size_t)(row0 + r)*128))[c4];
    }
    __syncthreads();

    const int tr = tid >> 4, tc = tid & 15;
    float acc[4][8];
#pragma unroll
    for (int i = 0; i < 4; i++)
#pragma unroll
        for (int j = 0; j < 8; j++) acc[i][j] = 0.f;

    gemm_tile<128>(As, Ws, tr, tc, acc);

    float4 b0 = *(const float4*)(bias + tc*8);
    float4 b1 = *(const float4*)(bias + tc*8 + 4);
#pragma unroll
    for (int i = 0; i < 4; i++) {
        int r = row0 + tr*4 + i;
        float4 o0, o1;
        o0.x = fmaxf(acc[i][0] + b0.x, 0.f);
        o0.y = fmaxf(acc[i][1] + b0.y, 0.f);
        o0.z = fmaxf(acc[i][2] + b0.z, 0.f);
        o0.w = fmaxf(acc[i][3] + b0.w, 0.f);
        o1.x = fmaxf(acc[i][4] + b1.x, 0.f);
        o1.y = fmaxf(acc[i][5] + b1.y, 0.f);
        o1.z = fmaxf(acc[i][6] + b1.z, 0.f);
        o1.w = fmaxf(acc[i][7] + b1.w, 0.f);
        *(float4*)(out + (size_t)r*128 + tc*8)     = o0;
        *(float4*)(out + (size_t)r*128 + tc*8 + 4) = o1;
    }
}

__global__ __launch_bounds__(256) void ln_kernel(
    float* __restrict__ X, const float* __restrict__ g, const float* __restrict__ bb) {
    int row  = blockIdx.x * 8 + (threadIdx.x >> 5);
    int lane = threadIdx.x & 31;
    float4* Xr = (float4*)(X + (size_t)row * 128);
    float4 v = Xr[lane];
    float s = v.x + v.y + v.z + v.w;
#pragma unroll
    for (int o = 16; o; o >>= 1) s += __shfl_xor_sync(0xffffffffu, s, o);
    float m = s * (1.f/128.f);
    float d0 = v.x - m, d1 = v.y - m, d2 = v.z - m, d3 = v.w - m;
    float q = d0*d0 + d1*d1 + d2*d2 + d3*d3;
#pragma unroll
    for (int o = 16; o; o >>= 1) q += __shfl_xor_sync(0xffffffffu, q, o);
    float inv = rsqrtf(q * (1.f/128.f) + 1e-5f);
    float4 gg = ((const float4*)g)[lane];
    float4 bv = ((const float4*)bb)[lane];
    v.x = d0*inv*gg.x + bv.x;
    v.y = d1*inv*gg.y + bv.y;
    v.z = d2*inv*gg.z + bv.z;
    v.w = d3*inv*gg.w + bv.w;
    Xr[lane] = v;
}

__global__ __launch_bounds__(256) void proj_kernel(
    const float* __restrict__ X,
    const float* __restrict__ Wq, const float* __restrict__ bq,
    const float* __restrict__ Wu, const float* __restrict__ bu,
    const float* __restrict__ wv, const float* __restrict__ bv,
    const float* __restrict__ mask,
    float* __restrict__ Q, float* __restrict__ U,
    float* __restrict__ Vs, float* __restrict__ Vsm) {
    extern __shared__ float smf[];
    float* Ws1 = smf;
    float* Ws2 = smf + 16384;
    float* As  = smf + 32768;
    float* wvs = As + 64*132;
    const int tid  = threadIdx.x;
    const int row0 = blockIdx.x * 64;

    const float4* Wq4 = (const float4*)Wq;
    const float4* Wu4 = (const float4*)Wu;
    float4* Ws14 = (float4*)Ws1;
    float4* Ws24 = (float4*)Ws2;
#pragma unroll
    for (int i = 0; i < 16; i++) {
        Ws14[tid + 256*i] = Wq4[tid + 256*i];
        Ws24[tid + 256*i] = Wu4[tid + 256*i];
    }
    if (tid < 32) ((float4*)wvs)[tid] = ((const float4*)wv)[tid];
#pragma unroll
    for (int i = 0; i < 8; i++) {
        int fi = tid + 256*i;
        int r = fi >> 5, c4 = fi & 31;
        *(float4*)(As + r*132 + c4*4) =
            ((const float4*)(X + (size_t)(row0 + r)*128))[c4];
    }
    __syncthreads();

    const int tr = tid >> 4, tc = tid & 15;

    {
        float acc[4][8];
#pragma unroll
        for (int i = 0; i < 4; i++)
#pragma unroll
            for (int j = 0; j < 8; j++) acc[i][j] = 0.f;
        gemm_tile<128>(As, Ws1, tr, tc, acc);
        float4 b0 = *(const float4*)(bq + tc*8);
        float4 b1 = *(const float4*)(bq + tc*8 + 4);
#pragma unroll
        for (int i = 0; i < 4; i++) {
            int r = row0 + tr*4 + i;
            float4 o0, o1;
            o0.x = acc[i][0] + b0.x; o0.y = acc[i][1] + b0.y;
            o0.z = acc[i][2] + b0.z; o0.w = acc[i][3] + b0.w;
            o1.x = acc[i][4] + b1.x; o1.y = acc[i][5] + b1.y;
            o1.z = acc[i][6] + b1.z; o1.w = acc[i][7] + b1.w;
            *(float4*)(Q + (size_t)r*128 + tc*8)     = o0;
            *(float4*)(Q + (size_t)r*128 + tc*8 + 4) = o1;
        }
    }
    {
        float acc[4][8];
#pragma unroll
        for (int i = 0; i < 4; i++)
#pragma unroll
            for (int j = 0; j < 8; j++) acc[i][j] = 0.f;
        gemm_tile<128>(As, Ws2, tr, tc, acc);
        float4 b0 = *(const float4*)(bu + tc*8);
        float4 b1 = *(const float4*)(bu + tc*8 + 4);
#pragma unroll
        for (int i = 0; i < 4; i++) {
            int r = row0 + tr*4 + i;
            float4 o0, o1;
            o0.x = fmaxf(acc[i][0] + b0.x, 0.f);
            o0.y = fmaxf(acc[i][1] + b0.y, 0.f);
            o0.z = fmaxf(acc[i][2] + b0.z, 0.f);
            o0.w = fmaxf(acc[i][3] + b0.w, 0.f);
            o1.x = fmaxf(acc[i][4] + b1.x, 0.f);
            o1.y = fmaxf(acc[i][5] + b1.y, 0.f);
            o1.z = fmaxf(acc[i][6] + b1.z, 0.f);
            o1.w = fmaxf(acc[i][7] + b1.w, 0.f);
            *(float4*)(U + (size_t)r*128 + tc*8)     = o0;
            *(float4*)(U + (size_t)r*128 + tc*8 + 4) = o1;
        }
    }
    if (tid < 64) {
        float s = 0.f;
        for (int k2 = 0; k2 < 128; k2++) s += As[tid*132 + k2] * wvs[k2];
        float v = fmaxf(s + bv[0], 0.f);
        int gr = row0 + tid;
        Vs[gr]  = v;
        Vsm[gr] = v * mask[gr];
    }
}

__device__ __forceinline__ float blk_reduce(float v, float* red, bool ismax) {
#pragma unroll
    for (int o = 16; o; o >>= 1) {
        float t = __shfl_xor_sync(0xffffffffu, v, o);
        v = ismax ? fmaxf(v, t) : v + t;
    }
    if ((threadIdx.x & 31) == 0) red[threadIdx.x >> 5] = v;
    __syncthreads();
    float r = red[0];
#pragma unroll
    for (int i = 1; i < 8; i++) r = ismax ? fmaxf(r, red[i]) : r + red[i];
    __syncthreads();
    return r;
}

__global__ __launch_bounds__(256) void pool_head_kernel(
    const float* __restrict__ Xg, const float* __restrict__ Yg,
    const float* __restrict__ fc_w, const float* __restrict__ fc_b,
    const float* __restrict__ out_w, const float* __restrict__ out_b,
    float* __restrict__ out) {
    __shared__ float w[1024];
    __shared__ float red[8];
    __shared__ float pp[256];
    __shared__ float xp[128];
    __shared__ float yp[128];
    const int tid = threadIdx.x;
    const int b   = blockIdx.x;

    for (int s = 0; s < 2; s++) {
        const float* S = (s ? Yg : Xg) + (size_t)b * SEQL * 128;
        float* dst = s ? yp : xp;
        for (int l = tid; l < SEQL; l += 256) {
            const float4* row = (const float4*)(S + (size_t)l*128);
            float acc = 0.f;
#pragma unroll
            for (int c = 0; c < 32; c++) {
                float4 v = row[c];
                acc += v.x*v.x + v.y*v.y + v.z*v.z + v.w*v.w;
            }
            w[l] = sqrtf(acc);
        }
        __syncthreads();
        float lm = -1e30f;
        for (int l = tid; l < SEQL; l += 256) lm = fmaxf(lm, w[l]);
        float mx = blk_reduce(lm, red, true);
        float ls = 0.f;
        for (int l = tid; l < SEQL; l += 256) { float e = expf(w[l] - mx); w[l] = e; ls += e; }
        float tot = blk_reduce(ls, red, false);
        float inv = 1.f / tot;

        int d = tid & 127, halfi = tid >> 7;
        float p = 0.f;
        for (int l = halfi; l < SEQL; l += 2) p += S[(size_t)l*128 + d] * w[l];
        pp[halfi*128 + d] = p;
        __syncthreads();
        if (tid < 128) dst[tid] = (pp[tid] + pp[128 + tid]) * inv;
        __syncthreads();
    }

    float h = 0.f;
    if (tid < 128) {
        h = fc_b[tid];
        for (int k2 = 0; k2 < 128; k2++) h += xp[k2] * fc_w[k2*128 + tid];
        for (int k2 = 0; k2 < 128; k2++) h += yp[k2] * fc_w[(128 + k2)*128 + tid];
        h = fmaxf(h, 0.f) * out_w[tid];
    }
    float tot = blk_reduce(h, red, false);
    if (tid == 0) out[b] = 1.f / (1.f + expf(-(tot + out_b[0])));
}

// ---------------- launch ----------------
extern "C" void kernel_launch(void* const* d_in, const int* in_sizes, int n_in,
                              void* d_out, int out_size) {
    (void)in_sizes; (void)n_in; (void)out_size;
    const float* seq1  = (const float*)d_in[0];
    const float* seq2  = (const float*)d_in[1];
    const float* mask1 = (const float*)d_in[2];
    const float* mask2 = (const float*)d_in[3];
    const float* l1_w  = (const float*)d_in[4];
    const float* l1_b  = (const float*)d_in[5];
    const float* l2_w  = (const float*)d_in[6];
    const float* l2_b  = (const float*)d_in[7];
    const float* ln1_g = (const float*)d_in[8];
    const float* ln1_b = (const float*)d_in[9];
    const float* ln2_g = (const float*)d_in[10];
    const float* ln2_b = (const float*)d_in[11];
    const float* wq_w  = (const float*)d_in[12];
    const float* wq_b  = (const float*)d_in[13];
    const float* wk_w  = (const float*)d_in[14];
    const float* wk_b  = (const float*)d_in[15];
    const float* wvx_w = (const float*)d_in[16];
    const float* wvx_b = (const float*)d_in[17];
    const float* wvy_w = (const float*)d_in[18];
    const float* wvy_b = (const float*)d_in[19];
    const float* wx_w  = (const float*)d_in[20];
    const float* wx_b  = (const float*)d_in[21];
    const float* wy_w  = (const float*)d_in[22];
    const float* wy_b  = (const float*)d_in[23];
    const float* fc_w  = (const float*)d_in[24];
    const float* fc_b  = (const float*)d_in[25];
    const float* out_w = (const float*)d_in[26];
    const float* out_b = (const float*)d_in[27];

    float *x, *y, *q, *k, *xu, *yu, *vx, *vy, *vxm, *vym;
    cudaGetSymbolAddress((void**)&x,  g_x);
    cudaGetSymbolAddress((void**)&y,  g_y);
    cudaGetSymbolAddress((void**)&q,  g_q);
    cudaGetSymbolAddress((void**)&k,  g_k);
    cudaGetSymbolAddress((void**)&xu, g_xu);
    cudaGetSymbolAddress((void**)&yu, g_yu);
    cudaGetSymbolAddress((void**)&vx, g_vx);
    cudaGetSymbolAddress((void**)&vy, g_vy);
    cudaGetSymbolAddress((void**)&vxm, g_vxm);
    cudaGetSymbolAddress((void**)&vym, g_vym);

    const int EMB_SMEM  = (16384 + 64*132) * 4;
    const int PROJ_SMEM = (2*16384 + 64*132 + 128) * 4;

    cudaFuncSetAttribute(embed_kernel,        cudaFuncAttributeMaxDynamicSharedMemorySize, EMB_SMEM);
    cudaFuncSetAttribute(proj_kernel,         cudaFuncAttributeMaxDynamicSharedMemorySize, PROJ_SMEM);
    cudaFuncSetAttribute(interact_mma_kernel, cudaFuncAttributeMaxDynamicSharedMemorySize, I_SMEM);

    embed_kernel<<<256, 256, EMB_SMEM>>>(seq1, l1_w, l1_b, x);
    embed_kernel<<<256, 256, EMB_SMEM>>>(seq2, l2_w, l2_b, y);

    for (int i = 0; i < 3; i++) {
        ln_kernel<<<2048, 256>>>(x, ln1_g + i*128, ln1_b + i*128);
        ln_kernel<<<2048, 256>>>(y, ln2_g + i*128, ln2_b + i*128);
        proj_kernel<<<256, 256, PROJ_SMEM>>>(x, wq_w + i*16384, wq_b + i*128,
                                             wx_w + i*16384, wx_b + i*128,
                                             wvx_w + i*128, wvx_b + i, mask1,
                                             q, xu, vx, vxm);
        proj_kernel<<<256, 256, PROJ_SMEM>>>(y, wk_w + i*16384, wk_b + i*128,
                                             wy_w + i*16384, wy_b + i*128,
                                             wvy_w + i*128, wvy_b + i, mask2,
                                             k, yu, vy, vym);
        dim3 ig(8, 16);
        interact_mma_kernel<<<ig, 256, I_SMEM>>>(q, k, yu, vxm, vy, x);
        interact_mma_kernel<<<ig, 256, I_SMEM>>>(k, q, xu, vym, vx, y);
    }
    pool_head_kernel<<<16, 256>>>(x, y, fc_w, fc_b, out_w, out_b, (float*)d_out);
}

// round 5
// speedup vs baseline: 3.0672x; 1.2985x over previous
#include <cuda_runtime.h>
#include <cuda_bf16.h>
#include <cstdint>
#include <math.h>

#define NROWS 16384        // B * L = 16 * 1024
#define SEQL  1024
#define SCALE_INV 0.08838834764831845f   // 1/sqrt(128)

// ---------------- persistent scratch ----------------
__device__ float g_x [NROWS*128];
__device__ float g_y [NROWS*128];
__device__ __nv_bfloat16 g_qh [NROWS*128];
__device__ __nv_bfloat16 g_ql [NROWS*128];
__device__ __nv_bfloat16 g_kh [NROWS*128];
__device__ __nv_bfloat16 g_kl [NROWS*128];
__device__ __nv_bfloat16 g_xuh[NROWS*128];
__device__ __nv_bfloat16 g_xul[NROWS*128];
__device__ __nv_bfloat16 g_yuh[NROWS*128];
__device__ __nv_bfloat16 g_yul[NROWS*128];
__device__ float g_vx [NROWS];
__device__ float g_vy [NROWS];
__device__ float g_vxm[NROWS];
__device__ float g_vym[NROWS];

__device__ __forceinline__ float sigmoidf_fast(float x) {
    return __fdividef(1.f, 1.f + __expf(-x));
}

__device__ __forceinline__ uint32_t smem_u32(const void* p) {
    uint32_t a;
    asm("{ .reg .u64 t; cvta.to.shared.u64 t, %1; cvt.u32.u64 %0, t; }" : "=r"(a) : "l"(p));
    return a;
}

__device__ __forceinline__ uint32_t packbf(__nv_bfloat16 a, __nv_bfloat16 b) {
    __nv_bfloat162 t(a, b);
    return *reinterpret_cast<uint32_t*>(&t);
}

// split two fp32 into hi/lo bf16 pairs (packed)
__device__ __forceinline__ void split2(float a, float b, uint32_t& hi, uint32_t& lo) {
    __nv_bfloat16 h0 = __float2bfloat16_rn(a), h1 = __float2bfloat16_rn(b);
    hi = packbf(h0, h1);
    lo = packbf(__float2bfloat16_rn(a - __bfloat162float(h0)),
                __float2bfloat16_rn(b - __bfloat162float(h1)));
}

__device__ __forceinline__ void ldsm_x4(uint32_t r[4], uint32_t addr) {
    asm volatile("ldmatrix.sync.aligned.m8n8.x4.shared.b16 {%0,%1,%2,%3}, [%4];"
                 : "=r"(r[0]), "=r"(r[1]), "=r"(r[2]), "=r"(r[3]) : "r"(addr));
}
__device__ __forceinline__ void ldsm_x4t(uint32_t r[4], uint32_t addr) {
    asm volatile("ldmatrix.sync.aligned.m8n8.x4.trans.shared.b16 {%0,%1,%2,%3}, [%4];"
                 : "=r"(r[0]), "=r"(r[1]), "=r"(r[2]), "=r"(r[3]) : "r"(addr));
}
__device__ __forceinline__ void mma_bf16(float c[4], const uint32_t a[4],
                                         uint32_t b0, uint32_t b1) {
    asm volatile(
        "mma.sync.aligned.m16n8k16.row.col.f32.bf16.bf16.f32 "
        "{%0,%1,%2,%3}, {%4,%5,%6,%7}, {%8,%9}, {%0,%1,%2,%3};"
        : "+f"(c[0]), "+f"(c[1]), "+f"(c[2]), "+f"(c[3])
        : "r"(a[0]), "r"(a[1]), "r"(a[2]), "r"(a[3]), "r"(b0), "r"(b1));
}

__device__ __forceinline__ void cp16(uint32_t saddr, const void* g) {
    asm volatile("cp.async.cg.shared.global [%0], [%1], 16;" :: "r"(saddr), "l"(g));
}
__device__ __forceinline__ void cp_commit() {
    asm volatile("cp.async.commit_group;" ::: "memory");
}
template<int N>
__device__ __forceinline__ void cp_wait() {
    asm volatile("cp.async.wait_group %0;" :: "n"(N) : "memory");
}

// ---- smem geometry (bf16 tiles, rows padded to 272B for conflict-free ldmatrix) ----
#define IROWB 272
#define QTILE (128 * IROWB)      // 34816
#define STILE (64 * IROWB)       // 17408

// interact smem
#define O_QH  0
#define O_QL  QTILE
#define O_ST  (2 * QTILE)
#define S_KH  0
#define S_KL  STILE
#define S_UH  (2 * STILE)
#define S_UL  (3 * STILE)
#define S_BS  (4 * STILE)        // 64 floats
#define STAGE (4 * STILE + 256)  // 69888
#define O_AS  (O_ST + 2 * STAGE)
#define I_SMEM (O_AS + 512)      // 209920

// proj smem
#define P_XH  0
#define P_XL  QTILE
#define P_WQH (2 * QTILE)
#define P_WQL (3 * QTILE)
#define P_WUH (4 * QTILE)
#define P_WUL (5 * QTILE)
#define P_WV  (6 * QTILE)        // 128 floats
#define P_SMEM (P_WV + 512)      // 209408

// =====================================================================
// interact: Out_i += aS_i * sum_j sigmoid((A_i . K_j)/sqrt(D)) * bS_j * U_j
// All A/K/U already bf16 hi/lo in gmem. 128 i-rows per CTA, 8 warps x 16 rows.
// 64-row j-tiles, cp.async double buffered.
// =====================================================================
__global__ __launch_bounds__(256) void interact_mma_kernel(
    const __nv_bfloat16* __restrict__ Ah, const __nv_bfloat16* __restrict__ Al,
    const __nv_bfloat16* __restrict__ Kh, const __nv_bfloat16* __restrict__ Kl,
    const __nv_bfloat16* __restrict__ Uh, const __nv_bfloat16* __restrict__ Ul,
    const float* __restrict__ aS, const float* __restrict__ bS,
    float* __restrict__ Out) {
    extern __shared__ __align__(16) char sm[];
    const int tid  = threadIdx.x;
    const int w    = tid >> 5, lane = tid & 31;
    const int b    = blockIdx.y;
    const int i0   = blockIdx.x * 128;
    const uint32_t sb = smem_u32(sm);
    float* aSs = (float*)(sm + O_AS);

    const size_t rowbase = (size_t)(b * SEQL + i0) * 128;

    // group A: Q hi/lo + aS + stage0
    for (int i = tid; i < 128 * 16; i += 256) {
        int r = i >> 4, c = i & 15;
        uint32_t ro = (uint32_t)(r * IROWB + c * 16);
        size_t go = rowbase + (size_t)r * 128 + c * 8;
        cp16(sb + O_QH + ro, Ah + go);
        cp16(sb + O_QL + ro, Al + go);
    }
    if (tid < 32) cp16(sb + O_AS + tid * 16, aS + b * SEQL + i0 + tid * 4);

    // stage issue helper (inlined via lambda-like macro loop)
#define ISSUE_STAGE(JT, BUF) do { \
        const size_t jb = (size_t)(b * SEQL + (JT) * 64) * 128; \
        uint32_t st = sb + O_ST + (BUF) * STAGE; \
        for (int i = tid; i < 64 * 16; i += 256) { \
            int r = i >> 4, c = i & 15; \
            uint32_t ro = (uint32_t)(r * IROWB + c * 16); \
            size_t go = jb + (size_t)r * 128 + c * 8; \
            cp16(st + S_KH + ro, Kh + go); \
            cp16(st + S_KL + ro, Kl + go); \
            cp16(st + S_UH + ro, Uh + go); \
            cp16(st + S_UL + ro, Ul + go); \
        } \
        if (tid < 16) cp16(st + S_BS + tid * 16, bS + b * SEQL + (JT) * 64 + tid * 4); \
    } while (0)

    ISSUE_STAGE(0, 0);
    cp_commit();

    float oacc[16][4];
#pragma unroll
    for (int n = 0; n < 16; n++)
#pragma unroll
        for (int c = 0; c < 4; c++) oacc[n][c] = 0.f;

    // fragment address components
    const uint32_t a_row  = 16 * w + (lane & 15);
    const uint32_t a_cadd = (lane & 16) ? 16 : 0;
    const uint32_t b_rsub = (uint32_t)(((lane & 16) ? 8 : 0) + (lane & 7));
    const uint32_t b_cadd = (lane & 8) ? 16 : 0;
    const uint32_t u_radd = (uint32_t)(lane & 15);
    const uint32_t u_cadd = (lane & 16) ? 16 : 0;

    for (int jt = 0; jt < 16; jt++) {
        if (jt + 1 < 16) {
            ISSUE_STAGE(jt + 1, (jt + 1) & 1);
            cp_commit();
            cp_wait<1>();
        } else {
            cp_wait<0>();
        }
        __syncthreads();

        const uint32_t st = sb + O_ST + (jt & 1) * STAGE;
        const float* bSs = (const float*)(sm + O_ST + (jt & 1) * STAGE + S_BS);

        // ---- GEMM1: S[16 x 64] = Q_w @ K^T over d=128 ----
        float sacc[8][4];
#pragma unroll
        for (int n = 0; n < 8; n++)
#pragma unroll
            for (int c = 0; c < 4; c++) sacc[n][c] = 0.f;

#pragma unroll
        for (int kt = 0; kt < 8; kt++) {
            uint32_t aoff = a_row * IROWB + kt * 32 + a_cadd;
            uint32_t ah[4], al[4];
            ldsm_x4(ah, sb + O_QH + aoff);
            ldsm_x4(al, sb + O_QL + aoff);
#pragma unroll
            for (int np = 0; np < 4; np++) {
                uint32_t boff = (16 * np + b_rsub) * IROWB + kt * 32 + b_cadd;
                uint32_t bh[4], bl[4];
                ldsm_x4(bh, st + S_KH + boff);
                ldsm_x4(bl, st + S_KL + boff);
                mma_bf16(sacc[2*np],   ah, bh[0], bh[1]);
                mma_bf16(sacc[2*np],   ah, bl[0], bl[1]);
                mma_bf16(sacc[2*np],   al, bh[0], bh[1]);
                mma_bf16(sacc[2*np+1], ah, bh[2], bh[3]);
                mma_bf16(sacc[2*np+1], ah, bl[2], bl[3]);
                mma_bf16(sacc[2*np+1], al, bh[2], bh[3]);
            }
        }

        // ---- P = sigmoid(S/sqrt(D)) * bS_j, split hi/lo in regs ----
        uint32_t ph[8][2], pl[8][2];
#pragma unroll
        for (int n = 0; n < 8; n++) {
            int j0 = 8 * n + 2 * (lane & 3);
            float2 bv = *(const float2*)(bSs + j0);
            float p00 = sigmoidf_fast(sacc[n][0] * SCALE_INV) * bv.x;
            float p01 = sigmoidf_fast(sacc[n][1] * SCALE_INV) * bv.y;
            float p10 = sigmoidf_fast(sacc[n][2] * SCALE_INV) * bv.x;
            float p11 = sigmoidf_fast(sacc[n][3] * SCALE_INV) * bv.y;
            split2(p00, p01, ph[n][0], pl[n][0]);
            split2(p10, p11, ph[n][1], pl[n][1]);
        }

        // ---- GEMM2: O[16 x 128] += P[16 x 64] @ U[64 x 128] ----
#pragma unroll
        for (int kt = 0; kt < 4; kt++) {
            uint32_t ah[4] = { ph[2*kt][0], ph[2*kt][1], ph[2*kt+1][0], ph[2*kt+1][1] };
            uint32_t al[4] = { pl[2*kt][0], pl[2*kt][1], pl[2*kt+1][0], pl[2*kt+1][1] };
#pragma unroll
            for (int np = 0; np < 8; np++) {
                uint32_t uoff = (16 * kt + u_radd) * IROWB + np * 32 + u_cadd;
                uint32_t uh[4], ul[4];
                ldsm_x4t(uh, st + S_UH + uoff);
                ldsm_x4t(ul, st + S_UL + uoff);
                mma_bf16(oacc[2*np],   ah, uh[0], uh[1]);
                mma_bf16(oacc[2*np],   ah, ul[0], ul[1]);
                mma_bf16(oacc[2*np],   al, uh[0], uh[1]);
                mma_bf16(oacc[2*np+1], ah, uh[2], uh[3]);
                mma_bf16(oacc[2*np+1], ah, ul[2], ul[3]);
                mma_bf16(oacc[2*np+1], al, uh[2], uh[3]);
            }
        }
        __syncthreads();   // all warps done with this stage before it is refilled
    }
#undef ISSUE_STAGE

    // ---- writeback: Out[i][d] += aS[i] * O[i][d] ----
    {
        int r0 = 16 * w + (lane >> 2), r1 = r0 + 8;
        float av0 = aSs[r0], av1 = aSs[r1];
        float* Ob = Out + rowbase;
#pragma unroll
        for (int n = 0; n < 16; n++) {
            int d = 8 * n + 2 * (lane & 3);
            float2 o0 = *(float2*)(Ob + (size_t)r0 * 128 + d);
            o0.x += av0 * oacc[n][0];
            o0.y += av0 * oacc[n][1];
            *(float2*)(Ob + (size_t)r0 * 128 + d) = o0;
            float2 o1 = *(float2*)(Ob + (size_t)r1 * 128 + d);
            o1.x += av1 * oacc[n][2];
            o1.y += av1 * oacc[n][3];
            *(float2*)(Ob + (size_t)r1 * 128 + d) = o1;
        }
    }
}

// =====================================================================
// proj (mma): Q = X@Wq + bq (bf16 hi/lo out); U = relu(X@Wu + bu) (bf16 hi/lo out);
// v = relu(X . wv + bv) gating scalars. 128 rows per CTA, 8 warps x 16 rows.
// =====================================================================
__global__ __launch_bounds__(256) void proj_mma_kernel(
    const float* __restrict__ X,
    const float* __restrict__ Wq, const float* __restrict__ bq,
    const float* __restrict__ Wu, const float* __restrict__ bu,
    const float* __restrict__ wv, const float* __restrict__ bv,
    const float* __restrict__ mask,
    __nv_bfloat16* __restrict__ Qh, __nv_bfloat16* __restrict__ Ql,
    __nv_bfloat16* __restrict__ Uh, __nv_bfloat16* __restrict__ Ul,
    float* __restrict__ Vs, float* __restrict__ Vsm) {
    extern __shared__ __align__(16) char sm[];
    const int tid = threadIdx.x;
    const int w   = tid >> 5, lane = tid & 31;
    const int row0 = blockIdx.x * 128;
    const uint32_t sb = smem_u32(sm);
    float* wvs = (float*)(sm + P_WV);

    // convert X rows and both weight matrices to bf16 hi/lo in smem
    for (int idx = tid; idx < 128 * 64; idx += 256) {
        int r = idx >> 6, cp = idx & 63;
        uint32_t off = (uint32_t)(r * IROWB + cp * 4);
        float2 xv = *(const float2*)(X + (size_t)(row0 + r) * 128 + cp * 2);
        uint32_t h, l;
        split2(xv.x, xv.y, h, l);
        *(uint32_t*)(sm + P_XH + off) = h;
        *(uint32_t*)(sm + P_XL + off) = l;
        float2 wq2 = *(const float2*)(Wq + (size_t)r * 128 + cp * 2);
        split2(wq2.x, wq2.y, h, l);
        *(uint32_t*)(sm + P_WQH + off) = h;
        *(uint32_t*)(sm + P_WQL + off) = l;
        float2 wu2 = *(const float2*)(Wu + (size_t)r * 128 + cp * 2);
        split2(wu2.x, wu2.y, h, l);
        *(uint32_t*)(sm + P_WUH + off) = h;
        *(uint32_t*)(sm + P_WUL + off) = l;
    }
    if (tid < 128) wvs[tid] = wv[tid];
    __syncthreads();

    // gating scalars: warp handles 16 rows, lane-parallel fp32 dot from gmem
    {
        float4 wv4 = ((const float4*)wvs)[lane];
        float bv0 = bv[0];
        for (int rr = 0; rr < 16; rr++) {
            int gr = row0 + 16 * w + rr;
            float4 xv = ((const float4*)(X + (size_t)gr * 128))[lane];
            float s = xv.x * wv4.x + xv.y * wv4.y + xv.z * wv4.z + xv.w * wv4.w;
#pragma unroll
            for (int o = 16; o; o >>= 1) s += __shfl_xor_sync(0xffffffffu, s, o);
            if (lane == 0) {
                float v = fmaxf(s + bv0, 0.f);
                Vs[gr]  = v;
                Vsm[gr] = v * mask[gr];
            }
        }
    }

    const uint32_t a_row  = 16 * w + (lane & 15);
    const uint32_t a_cadd = (lane & 16) ? 16 : 0;
    const uint32_t u_radd = (uint32_t)(lane & 15);
    const uint32_t u_cadd = (lane & 16) ? 16 : 0;
    const int r0 = 16 * w + (lane >> 2), r1 = r0 + 8;

    // ---- GEMM Q then GEMM U (sequential to bound registers) ----
    for (int g = 0; g < 2; g++) {
        const uint32_t WH = g ? P_WUH : P_WQH;
        const uint32_t WL = g ? P_WUL : P_WQL;
        float acc[16][4];
#pragma unroll
        for (int n = 0; n < 16; n++)
#pragma unroll
            for (int c = 0; c < 4; c++) acc[n][c] = 0.f;

#pragma unroll
        for (int kt = 0; kt < 8; kt++) {
            uint32_t aoff = a_row * IROWB + kt * 32 + a_cadd;
            uint32_t ah[4], al[4];
            ldsm_x4(ah, sb + P_XH + aoff);
            ldsm_x4(al, sb + P_XL + aoff);
#pragma unroll
            for (int np = 0; np < 8; np++) {
                uint32_t boff = (16 * kt + u_radd) * IROWB + np * 32 + u_cadd;
                uint32_t bh[4], bl[4];
                ldsm_x4t(bh, sb + WH + boff);
                ldsm_x4t(bl, sb + WL + boff);
                mma_bf16(acc[2*np],   ah, bh[0], bh[1]);
                mma_bf16(acc[2*np],   ah, bl[0], bl[1]);
                mma_bf16(acc[2*np],   al, bh[0], bh[1]);
                mma_bf16(acc[2*np+1], ah, bh[2], bh[3]);
                mma_bf16(acc[2*np+1], ah, bl[2], bl[3]);
                mma_bf16(acc[2*np+1], al, bh[2], bh[3]);
            }
        }

        const float* bias = g ? bu : bq;
        __nv_bfloat16* Oh = g ? Uh : Qh;
        __nv_bfloat16* Ol = g ? Ul : Ql;
#pragma unroll
        for (int n = 0; n < 16; n++) {
            int d = 8 * n + 2 * (lane & 3);
            float2 bb = *(const float2*)(bias + d);
            float v00 = acc[n][0] + bb.x, v01 = acc[n][1] + bb.y;
            float v10 = acc[n][2] + bb.x, v11 = acc[n][3] + bb.y;
            if (g) {
                v00 = fmaxf(v00, 0.f); v01 = fmaxf(v01, 0.f);
                v10 = fmaxf(v10, 0.f); v11 = fmaxf(v11, 0.f);
            }
            uint32_t h, l;
            split2(v00, v01, h, l);
            *(uint32_t*)(Oh + (size_t)(row0 + r0) * 128 + d) = h;
            *(uint32_t*)(Ol + (size_t)(row0 + r0) * 128 + d) = l;
            split2(v10, v11, h, l);
            *(uint32_t*)(Oh + (size_t)(row0 + r1) * 128 + d) = h;
            *(uint32_t*)(Ol + (size_t)(row0 + r1) * 128 + d) = l;
        }
    }
}

// ================= SIMT kernels (known-good) =================

template<int WSTRIDE>
__device__ __forceinline__ void gemm_tile(const float* __restrict__ As,
                                          const float* __restrict__ Ws,
                                          int tr, int tc, float acc[4][8]) {
    for (int k = 0; k < 128; k += 4) {
        float a[4][4];
#pragma unroll
        for (int i = 0; i < 4; i++) {
            float4 av = *(const float4*)(As + (tr*4 + i)*132 + k);
            a[i][0] = av.x; a[i][1] = av.y; a[i][2] = av.z; a[i][3] = av.w;
        }
#pragma unroll
        for (int kk = 0; kk < 4; kk++) {
            float4 w0 = *(const float4*)(Ws + (k + kk)*WSTRIDE + tc*8);
            float4 w1 = *(const float4*)(Ws + (k + kk)*WSTRIDE + tc*8 + 4);
#pragma unroll
            for (int i = 0; i < 4; i++) {
                float av = a[i][kk];
                acc[i][0] += av*w0.x; acc[i][1] += av*w0.y;
                acc[i][2] += av*w0.z; acc[i][3] += av*w0.w;
                acc[i][4] += av*w1.x; acc[i][5] += av*w1.y;
                acc[i][6] += av*w1.z; acc[i][7] += av*w1.w;
            }
        }
    }
}

__global__ __launch_bounds__(256) void embed_kernel(
    const float* __restrict__ A, const float* __restrict__ W,
    const float* __restrict__ bias, float* __restrict__ out) {
    extern __shared__ float smf[];
    float* Ws = smf;
    float* As = smf + 16384;
    const int tid  = threadIdx.x;
    const int row0 = blockIdx.x * 64;

    const float4* W4 = (const float4*)W;
    float4* Ws4 = (float4*)Ws;
#pragma unroll
    for (int i = 0; i < 16; i++) Ws4[tid + 256*i] = W4[tid + 256*i];
#pragma unroll
    for (int i = 0; i < 8; i++) {
        int fi = tid + 256*i;
        int r = fi >> 5, c4 = fi & 31;
        *(float4*)(As + r*132 + c4*4) =
            ((const float4*)(A + (size_t)(row0 + r)*128))[c4];
    }
    __syncthreads();

    const int tr = tid >> 4, tc = tid & 15;
    float acc[4][8];
#pragma unroll
    for (int i = 0; i < 4; i++)
#pragma unroll
        for (int j = 0; j < 8; j++) acc[i][j] = 0.f;

    gemm_tile<128>(As, Ws, tr, tc, acc);

    float4 b0 = *(const float4*)(bias + tc*8);
    float4 b1 = *(const float4*)(bias + tc*8 + 4);
#pragma unroll
    for (int i = 0; i < 4; i++) {
        int r = row0 + tr*4 + i;
        float4 o0, o1;
        o0.x = fmaxf(acc[i][0] + b0.x, 0.f);
        o0.y = fmaxf(acc[i][1] + b0.y, 0.f);
        o0.z = fmaxf(acc[i][2] + b0.z, 0.f);
        o0.w = fmaxf(acc[i][3] + b0.w, 0.f);
        o1.x = fmaxf(acc[i][4] + b1.x, 0.f);
        o1.y = fmaxf(acc[i][5] + b1.y, 0.f);
        o1.z = fmaxf(acc[i][6] + b1.z, 0.f);
        o1.w = fmaxf(acc[i][7] + b1.w, 0.f);
        *(float4*)(out + (size_t)r*128 + tc*8)     = o0;
        *(float4*)(out + (size_t)r*128 + tc*8 + 4) = o1;
    }
}

__global__ __launch_bounds__(256) void ln_kernel(
    float* __restrict__ X, const float* __restrict__ g, const float* __restrict__ bb) {
    int row  = blockIdx.x * 8 + (threadIdx.x >> 5);
    int lane = threadIdx.x & 31;
    float4* Xr = (float4*)(X + (size_t)row * 128);
    float4 v = Xr[lane];
    float s = v.x + v.y + v.z + v.w;
#pragma unroll
    for (int o = 16; o; o >>= 1) s += __shfl_xor_sync(0xffffffffu, s, o);
    float m = s * (1.f/128.f);
    float d0 = v.x - m, d1 = v.y - m, d2 = v.z - m, d3 = v.w - m;
    float q = d0*d0 + d1*d1 + d2*d2 + d3*d3;
#pragma unroll
    for (int o = 16; o; o >>= 1) q += __shfl_xor_sync(0xffffffffu, q, o);
    float inv = rsqrtf(q * (1.f/128.f) + 1e-5f);
    float4 gg = ((const float4*)g)[lane];
    float4 bv = ((const float4*)bb)[lane];
    v.x = d0*inv*gg.x + bv.x;
    v.y = d1*inv*gg.y + bv.y;
    v.z = d2*inv*gg.z + bv.z;
    v.w = d3*inv*gg.w + bv.w;
    Xr[lane] = v;
}

__device__ __forceinline__ float blk_reduce(float v, float* red, bool ismax) {
#pragma unroll
    for (int o = 16; o; o >>= 1) {
        float t = __shfl_xor_sync(0xffffffffu, v, o);
        v = ismax ? fmaxf(v, t) : v + t;
    }
    if ((threadIdx.x & 31) == 0) red[threadIdx.x >> 5] = v;
    __syncthreads();
    float r = red[0];
#pragma unroll
    for (int i = 1; i < 8; i++) r = ismax ? fmaxf(r, red[i]) : r + red[i];
    __syncthreads();
    return r;
}

__global__ __launch_bounds__(256) void pool_head_kernel(
    const float* __restrict__ Xg, const float* __restrict__ Yg,
    const float* __restrict__ fc_w, const float* __restrict__ fc_b,
    const float* __restrict__ out_w, const float* __restrict__ out_b,
    float* __restrict__ out) {
    __shared__ float w[1024];
    __shared__ float red[8];
    __shared__ float pp[256];
    __shared__ float xp[128];
    __shared__ float yp[128];
    const int tid = threadIdx.x;
    const int b   = blockIdx.x;

    for (int s = 0; s < 2; s++) {
        const float* S = (s ? Yg : Xg) + (size_t)b * SEQL * 128;
        float* dst = s ? yp : xp;
        for (int l = tid; l < SEQL; l += 256) {
            const float4* row = (const float4*)(S + (size_t)l*128);
            float acc = 0.f;
#pragma unroll
            for (int c = 0; c < 32; c++) {
                float4 v = row[c];
                acc += v.x*v.x + v.y*v.y + v.z*v.z + v.w*v.w;
            }
            w[l] = sqrtf(acc);
        }
        __syncthreads();
        float lm = -1e30f;
        for (int l = tid; l < SEQL; l += 256) lm = fmaxf(lm, w[l]);
        float mx = blk_reduce(lm, red, true);
        float ls = 0.f;
        for (int l = tid; l < SEQL; l += 256) { float e = expf(w[l] - mx); w[l] = e; ls += e; }
        float tot = blk_reduce(ls, red, false);
        float inv = 1.f / tot;

        int d = tid & 127, halfi = tid >> 7;
        float p = 0.f;
        for (int l = halfi; l < SEQL; l += 2) p += S[(size_t)l*128 + d] * w[l];
        pp[halfi*128 + d] = p;
        __syncthreads();
        if (tid < 128) dst[tid] = (pp[tid] + pp[128 + tid]) * inv;
        __syncthreads();
    }

    float h = 0.f;
    if (tid < 128) {
        h = fc_b[tid];
        for (int k2 = 0; k2 < 128; k2++) h += xp[k2] * fc_w[k2*128 + tid];
        for (int k2 = 0; k2 < 128; k2++) h += yp[k2] * fc_w[(128 + k2)*128 + tid];
        h = fmaxf(h, 0.f) * out_w[tid];
    }
    float tot = blk_reduce(h, red, false);
    if (tid == 0) out[b] = 1.f / (1.f + expf(-(tot + out_b[0])));
}

// ---------------- launch ----------------
extern "C" void kernel_launch(void* const* d_in, const int* in_sizes, int n_in,
                              void* d_out, int out_size) {
    (void)in_sizes; (void)n_in; (void)out_size;
    const float* seq1  = (const float*)d_in[0];
    const float* seq2  = (const float*)d_in[1];
    const float* mask1 = (const float*)d_in[2];
    const float* mask2 = (const float*)d_in[3];
    const float* l1_w  = (const float*)d_in[4];
    const float* l1_b  = (const float*)d_in[5];
    const float* l2_w  = (const float*)d_in[6];
    const float* l2_b  = (const float*)d_in[7];
    const float* ln1_g = (const float*)d_in[8];
    const float* ln1_b = (const float*)d_in[9];
    const float* ln2_g = (const float*)d_in[10];
    const float* ln2_b = (const float*)d_in[11];
    const float* wq_w  = (const float*)d_in[12];
    const float* wq_b  = (const float*)d_in[13];
    const float* wk_w  = (const float*)d_in[14];
    const float* wk_b  = (const float*)d_in[15];
    const float* wvx_w = (const float*)d_in[16];
    const float* wvx_b = (const float*)d_in[17];
    const float* wvy_w = (const float*)d_in[18];
    const float* wvy_b = (const float*)d_in[19];
    const float* wx_w  = (const float*)d_in[20];
    const float* wx_b  = (const float*)d_in[21];
    const float* wy_w  = (const float*)d_in[22];
    const float* wy_b  = (const float*)d_in[23];
    const float* fc_w  = (const float*)d_in[24];
    const float* fc_b  = (const float*)d_in[25];
    const float* out_w = (const float*)d_in[26];
    const float* out_b = (const float*)d_in[27];

    float *x, *y, *vx, *vy, *vxm, *vym;
    __nv_bfloat16 *qh, *ql, *kh, *kl, *xuh, *xul, *yuh, *yul;
    cudaGetSymbolAddress((void**)&x,   g_x);
    cudaGetSymbolAddress((void**)&y,   g_y);
    cudaGetSymbolAddress((void**)&qh,  g_qh);
    cudaGetSymbolAddress((void**)&ql,  g_ql);
    cudaGetSymbolAddress((void**)&kh,  g_kh);
    cudaGetSymbolAddress((void**)&kl,  g_kl);
    cudaGetSymbolAddress((void**)&xuh, g_xuh);
    cudaGetSymbolAddress((void**)&xul, g_xul);
    cudaGetSymbolAddress((void**)&yuh, g_yuh);
    cudaGetSymbolAddress((void**)&yul, g_yul);
    cudaGetSymbolAddress((void**)&vx,  g_vx);
    cudaGetSymbolAddress((void**)&vy,  g_vy);
    cudaGetSymbolAddress((void**)&vxm, g_vxm);
    cudaGetSymbolAddress((void**)&vym, g_vym);

    const int EMB_SMEM = (16384 + 64*132) * 4;

    cudaFuncSetAttribute(embed_kernel,        cudaFuncAttributeMaxDynamicSharedMemorySize, EMB_SMEM);
    cudaFuncSetAttribute(proj_mma_kernel,     cudaFuncAttributeMaxDynamicSharedMemorySize, P_SMEM);
    cudaFuncSetAttribute(interact_mma_kernel, cudaFuncAttributeMaxDynamicSharedMemorySize, I_SMEM);

    embed_kernel<<<256, 256, EMB_SMEM>>>(seq1, l1_w, l1_b, x);
    embed_kernel<<<256, 256, EMB_SMEM>>>(seq2, l2_w, l2_b, y);

    for (int i = 0; i < 3; i++) {
        ln_kernel<<<2048, 256>>>(x, ln1_g + i*128, ln1_b + i*128);
        ln_kernel<<<2048, 256>>>(y, ln2_g + i*128, ln2_b + i*128);
        proj_mma_kernel<<<128, 256, P_SMEM>>>(x, wq_w + i*16384, wq_b + i*128,
                                              wx_w + i*16384, wx_b + i*128,
                                              wvx_w + i*128, wvx_b + i, mask1,
                                              qh, ql, xuh, xul, vx, vxm);
        proj_mma_kernel<<<128, 256, P_SMEM>>>(y, wk_w + i*16384, wk_b + i*128,
                                              wy_w + i*16384, wy_b + i*128,
                                              wvy_w + i*128, wvy_b + i, mask2,
                                              kh, kl, yuh, yul, vy, vym);
        dim3 ig(8, 16);
        interact_mma_kernel<<<ig, 256, I_SMEM>>>(qh, ql, kh, kl, yuh, yul, vxm, vy, x);
        interact_mma_kernel<<<ig, 256, I_SMEM>>>(kh, kl, qh, ql, xuh, xul, vym, vx, y);
    }
    pool_head_kernel<<<16, 256>>>(x, y, fc_w, fc_b, out_w, out_b, (float*)d_out);
}

// round 6
// speedup vs baseline: 3.1313x; 1.0209x over previous
#include <cuda_runtime.h>
#include <cuda_bf16.h>
#include <cstdint>
#include <math.h>

#define NROWS 16384        // B * L = 16 * 1024
#define SEQL  1024
#define SCALE_INV 0.08838834764831845f   // 1/sqrt(128)

// ---------------- persistent scratch ----------------
__device__ float g_x [NROWS*128];
__device__ float g_y [NROWS*128];
__device__ __nv_bfloat16 g_qh [NROWS*128];
__device__ __nv_bfloat16 g_ql [NROWS*128];
__device__ __nv_bfloat16 g_kh [NROWS*128];
__device__ __nv_bfloat16 g_kl [NROWS*128];
__device__ __nv_bfloat16 g_xuh[NROWS*128];
__device__ __nv_bfloat16 g_xul[NROWS*128];
__device__ __nv_bfloat16 g_yuh[NROWS*128];
__device__ __nv_bfloat16 g_yul[NROWS*128];
__device__ float g_vx [NROWS];
__device__ float g_vy [NROWS];
__device__ float g_vxm[NROWS];
__device__ float g_vym[NROWS];

__device__ __forceinline__ float sigmoidf_fast(float x) {
    return __fdividef(1.f, 1.f + __expf(-x));
}

__device__ __forceinline__ uint32_t smem_u32(const void* p) {
    uint32_t a;
    asm("{ .reg .u64 t; cvta.to.shared.u64 t, %1; cvt.u32.u64 %0, t; }" : "=r"(a) : "l"(p));
    return a;
}

__device__ __forceinline__ uint32_t packbf(__nv_bfloat16 a, __nv_bfloat16 b) {
    __nv_bfloat162 t(a, b);
    return *reinterpret_cast<uint32_t*>(&t);
}

__device__ __forceinline__ void split2(float a, float b, uint32_t& hi, uint32_t& lo) {
    __nv_bfloat16 h0 = __float2bfloat16_rn(a), h1 = __float2bfloat16_rn(b);
    hi = packbf(h0, h1);
    lo = packbf(__float2bfloat16_rn(a - __bfloat162float(h0)),
                __float2bfloat16_rn(b - __bfloat162float(h1)));
}

__device__ __forceinline__ void ldsm_x4(uint32_t r[4], uint32_t addr) {
    asm volatile("ldmatrix.sync.aligned.m8n8.x4.shared.b16 {%0,%1,%2,%3}, [%4];"
                 : "=r"(r[0]), "=r"(r[1]), "=r"(r[2]), "=r"(r[3]) : "r"(addr));
}
__device__ __forceinline__ void ldsm_x4t(uint32_t r[4], uint32_t addr) {
    asm volatile("ldmatrix.sync.aligned.m8n8.x4.trans.shared.b16 {%0,%1,%2,%3}, [%4];"
                 : "=r"(r[0]), "=r"(r[1]), "=r"(r[2]), "=r"(r[3]) : "r"(addr));
}
__device__ __forceinline__ void mma_bf16(float c[4], const uint32_t a[4],
                                         uint32_t b0, uint32_t b1) {
    asm volatile(
        "mma.sync.aligned.m16n8k16.row.col.f32.bf16.bf16.f32 "
        "{%0,%1,%2,%3}, {%4,%5,%6,%7}, {%8,%9}, {%0,%1,%2,%3};"
        : "+f"(c[0]), "+f"(c[1]), "+f"(c[2]), "+f"(c[3])
        : "r"(a[0]), "r"(a[1]), "r"(a[2]), "r"(a[3]), "r"(b0), "r"(b1));
}

__device__ __forceinline__ void cp16(uint32_t saddr, const void* g) {
    asm volatile("cp.async.cg.shared.global [%0], [%1], 16;" :: "r"(saddr), "l"(g));
}
__device__ __forceinline__ void cp_commit() {
    asm volatile("cp.async.commit_group;" ::: "memory");
}
template<int N>
__device__ __forceinline__ void cp_wait() {
    asm volatile("cp.async.wait_group %0;" :: "n"(N) : "memory");
}

// ---- smem geometry ----
#define IROWB 272
#define QTILE (128 * IROWB)      // 34816
#define STILE (64 * IROWB)       // 17408

// interact smem
#define O_QH  0
#define O_QL  QTILE
#define O_ST  (2 * QTILE)
#define S_KH  0
#define S_KL  STILE
#define S_UH  (2 * STILE)
#define S_UL  (3 * STILE)
#define S_BS  (4 * STILE)
#define STAGE (4 * STILE + 256)
#define O_AS  (O_ST + 2 * STAGE)
#define I_SMEM (O_AS + 512)      // 209920

// proj smem
#define P_XH  0
#define P_XL  QTILE
#define P_WQH (2 * QTILE)
#define P_WQL (3 * QTILE)
#define P_WUH (4 * QTILE)
#define P_WUL (5 * QTILE)
#define P_WV  (6 * QTILE)
#define P_SMEM (P_WV + 512)      // 209408

// embed smem
#define E_XH  0
#define E_XL  QTILE
#define E_WH  (2 * QTILE)
#define E_WL  (3 * QTILE)
#define E_SMEM (4 * QTILE)       // 139264

// =====================================================================
// interact: both passes in one launch (blockIdx.z selects x-pass / y-pass)
// =====================================================================
__global__ __launch_bounds__(256) void interact_mma_kernel(
    const __nv_bfloat16* __restrict__ qh, const __nv_bfloat16* __restrict__ ql,
    const __nv_bfloat16* __restrict__ kh, const __nv_bfloat16* __restrict__ kl,
    const __nv_bfloat16* __restrict__ xuh, const __nv_bfloat16* __restrict__ xul,
    const __nv_bfloat16* __restrict__ yuh, const __nv_bfloat16* __restrict__ yul,
    const float* __restrict__ vxm, const float* __restrict__ vy,
    const float* __restrict__ vym, const float* __restrict__ vx,
    float* __restrict__ xO, float* __restrict__ yO) {
    extern __shared__ __align__(16) char sm[];
    const int tid  = threadIdx.x;
    const int w    = tid >> 5, lane = tid & 31;
    const int b    = blockIdx.y;
    const int i0   = blockIdx.x * 128;
    const int z    = blockIdx.z;
    const uint32_t sb = smem_u32(sm);
    float* aSs = (float*)(sm + O_AS);

    const __nv_bfloat16* Ah = z ? kh  : qh;
    const __nv_bfloat16* Al = z ? kl  : ql;
    const __nv_bfloat16* Kh = z ? qh  : kh;
    const __nv_bfloat16* Kl = z ? ql  : kl;
    const __nv_bfloat16* Uh = z ? xuh : yuh;
    const __nv_bfloat16* Ul = z ? xul : yul;
    const float* aS = z ? vym : vxm;
    const float* bS = z ? vx  : vy;
    float* Out      = z ? yO  : xO;

    const size_t rowbase = (size_t)(b * SEQL + i0) * 128;

    for (int i = tid; i < 128 * 16; i += 256) {
        int r = i >> 4, c = i & 15;
        uint32_t ro = (uint32_t)(r * IROWB + c * 16);
        size_t go = rowbase + (size_t)r * 128 + c * 8;
        cp16(sb + O_QH + ro, Ah + go);
        cp16(sb + O_QL + ro, Al + go);
    }
    if (tid < 32) cp16(sb + O_AS + tid * 16, aS + b * SEQL + i0 + tid * 4);

#define ISSUE_STAGE(JT, BUF) do { \
        const size_t jb = (size_t)(b * SEQL + (JT) * 64) * 128; \
        uint32_t st = sb + O_ST + (BUF) * STAGE; \
        for (int i = tid; i < 64 * 16; i += 256) { \
            int r = i >> 4, c = i & 15; \
            uint32_t ro = (uint32_t)(r * IROWB + c * 16); \
            size_t go = jb + (size_t)r * 128 + c * 8; \
            cp16(st + S_KH + ro, Kh + go); \
            cp16(st + S_KL + ro, Kl + go); \
            cp16(st + S_UH + ro, Uh + go); \
            cp16(st + S_UL + ro, Ul + go); \
        } \
        if (tid < 16) cp16(st + S_BS + tid * 16, bS + b * SEQL + (JT) * 64 + tid * 4); \
    } while (0)

    ISSUE_STAGE(0, 0);
    cp_commit();

    float oacc[16][4];
#pragma unroll
    for (int n = 0; n < 16; n++)
#pragma unroll
        for (int c = 0; c < 4; c++) oacc[n][c] = 0.f;

    const uint32_t a_row  = 16 * w + (lane & 15);
    const uint32_t a_cadd = (lane & 16) ? 16 : 0;
    const uint32_t b_rsub = (uint32_t)(((lane & 16) ? 8 : 0) + (lane & 7));
    const uint32_t b_cadd = (lane & 8) ? 16 : 0;
    const uint32_t u_radd = (uint32_t)(lane & 15);
    const uint32_t u_cadd = (lane & 16) ? 16 : 0;

    for (int jt = 0; jt < 16; jt++) {
        if (jt + 1 < 16) {
            ISSUE_STAGE(jt + 1, (jt + 1) & 1);
            cp_commit();
            cp_wait<1>();
        } else {
            cp_wait<0>();
        }
        __syncthreads();

        const uint32_t st = sb + O_ST + (jt & 1) * STAGE;
        const float* bSs = (const float*)(sm + O_ST + (jt & 1) * STAGE + S_BS);

        float sacc[8][4];
#pragma unroll
        for (int n = 0; n < 8; n++)
#pragma unroll
            for (int c = 0; c < 4; c++) sacc[n][c] = 0.f;

#pragma unroll
        for (int kt = 0; kt < 8; kt++) {
            uint32_t aoff = a_row * IROWB + kt * 32 + a_cadd;
            uint32_t ah[4], al[4];
            ldsm_x4(ah, sb + O_QH + aoff);
            ldsm_x4(al, sb + O_QL + aoff);
#pragma unroll
            for (int np = 0; np < 4; np++) {
                uint32_t boff = (16 * np + b_rsub) * IROWB + kt * 32 + b_cadd;
                uint32_t bh[4], bl[4];
                ldsm_x4(bh, st + S_KH + boff);
                ldsm_x4(bl, st + S_KL + boff);
                mma_bf16(sacc[2*np],   ah, bh[0], bh[1]);
                mma_bf16(sacc[2*np],   ah, bl[0], bl[1]);
                mma_bf16(sacc[2*np],   al, bh[0], bh[1]);
                mma_bf16(sacc[2*np+1], ah, bh[2], bh[3]);
                mma_bf16(sacc[2*np+1], ah, bl[2], bl[3]);
                mma_bf16(sacc[2*np+1], al, bh[2], bh[3]);
            }
        }

        uint32_t ph[8][2], pl[8][2];
#pragma unroll
        for (int n = 0; n < 8; n++) {
            int j0 = 8 * n + 2 * (lane & 3);
            float2 bv = *(const float2*)(bSs + j0);
            float p00 = sigmoidf_fast(sacc[n][0] * SCALE_INV) * bv.x;
            float p01 = sigmoidf_fast(sacc[n][1] * SCALE_INV) * bv.y;
            float p10 = sigmoidf_fast(sacc[n][2] * SCALE_INV) * bv.x;
            float p11 = sigmoidf_fast(sacc[n][3] * SCALE_INV) * bv.y;
            split2(p00, p01, ph[n][0], pl[n][0]);
            split2(p10, p11, ph[n][1], pl[n][1]);
        }

#pragma unroll
        for (int kt = 0; kt < 4; kt++) {
            uint32_t ah[4] = { ph[2*kt][0], ph[2*kt][1], ph[2*kt+1][0], ph[2*kt+1][1] };
            uint32_t al[4] = { pl[2*kt][0], pl[2*kt][1], pl[2*kt+1][0], pl[2*kt+1][1] };
#pragma unroll
            for (int np = 0; np < 8; np++) {
                uint32_t uoff = (16 * kt + u_radd) * IROWB + np * 32 + u_cadd;
                uint32_t uh[4], ul[4];
                ldsm_x4t(uh, st + S_UH + uoff);
                ldsm_x4t(ul, st + S_UL + uoff);
                mma_bf16(oacc[2*np],   ah, uh[0], uh[1]);
                mma_bf16(oacc[2*np],   ah, ul[0], ul[1]);
                mma_bf16(oacc[2*np],   al, uh[0], uh[1]);
                mma_bf16(oacc[2*np+1], ah, uh[2], uh[3]);
                mma_bf16(oacc[2*np+1], ah, ul[2], ul[3]);
                mma_bf16(oacc[2*np+1], al, uh[2], uh[3]);
            }
        }
        __syncthreads();
    }
#undef ISSUE_STAGE

    {
        int r0 = 16 * w + (lane >> 2), r1 = r0 + 8;
        float av0 = aSs[r0], av1 = aSs[r1];
        float* Ob = Out + rowbase;
#pragma unroll
        for (int n = 0; n < 16; n++) {
            int d = 8 * n + 2 * (lane & 3);
            float2 o0 = *(float2*)(Ob + (size_t)r0 * 128 + d);
            o0.x += av0 * oacc[n][0];
            o0.y += av0 * oacc[n][1];
            *(float2*)(Ob + (size_t)r0 * 128 + d) = o0;
            float2 o1 = *(float2*)(Ob + (size_t)r1 * 128 + d);
            o1.x += av1 * oacc[n][2];
            o1.y += av1 * oacc[n][3];
            *(float2*)(Ob + (size_t)r1 * 128 + d) = o1;
        }
    }
}

// =====================================================================
// proj (mma), both sides in one launch (blockIdx.y selects)
// =====================================================================
__global__ __launch_bounds__(256) void proj_mma_kernel(
    const float* __restrict__ X1, const float* __restrict__ X2,
    const float* __restrict__ Wq1, const float* __restrict__ bq1,
    const float* __restrict__ Wu1, const float* __restrict__ bu1,
    const float* __restrict__ wv1, const float* __restrict__ bv1,
    const float* __restrict__ Wq2, const float* __restrict__ bq2,
    const float* __restrict__ Wu2, const float* __restrict__ bu2,
    const float* __restrict__ wv2, const float* __restrict__ bv2,
    const float* __restrict__ mask1, const float* __restrict__ mask2,
    __nv_bfloat16* __restrict__ qh, __nv_bfloat16* __restrict__ ql,
    __nv_bfloat16* __restrict__ xuh, __nv_bfloat16* __restrict__ xul,
    __nv_bfloat16* __restrict__ kh, __nv_bfloat16* __restrict__ kl,
    __nv_bfloat16* __restrict__ yuh, __nv_bfloat16* __restrict__ yul,
    float* __restrict__ vx, float* __restrict__ vxm,
    float* __restrict__ vy, float* __restrict__ vym) {
    extern __shared__ __align__(16) char sm[];
    const int tid = threadIdx.x;
    const int w   = tid >> 5, lane = tid & 31;
    const int row0 = blockIdx.x * 128;
    const int z = blockIdx.y;
    const uint32_t sb = smem_u32(sm);
    float* wvs = (float*)(sm + P_WV);

    const float* X  = z ? X2 : X1;
    const float* Wq = z ? Wq2 : Wq1;
    const float* bq = z ? bq2 : bq1;
    const float* Wu = z ? Wu2 : Wu1;
    const float* bu = z ? bu2 : bu1;
    const float* wv = z ? wv2 : wv1;
    const float* bv = z ? bv2 : bv1;
    const float* mask = z ? mask2 : mask1;
    __nv_bfloat16* Qh = z ? kh : qh;
    __nv_bfloat16* Ql = z ? kl : ql;
    __nv_bfloat16* Uh = z ? yuh : xuh;
    __nv_bfloat16* Ul = z ? yul : xul;
    float* Vs  = z ? vy : vx;
    float* Vsm = z ? vym : vxm;

    // convert X rows and both weight matrices to bf16 hi/lo in smem (float4 loads)
    for (int idx = tid; idx < 128 * 32; idx += 256) {
        int r = idx >> 5, cq = idx & 31;
        uint32_t off = (uint32_t)(r * IROWB + cq * 8);
        uint32_t h0, l0, h1, l1;
        float4 xv = *(const float4*)(X + (size_t)(row0 + r) * 128 + cq * 4);
        split2(xv.x, xv.y, h0, l0);
        split2(xv.z, xv.w, h1, l1);
        *(uint2*)(sm + P_XH + off) = make_uint2(h0, h1);
        *(uint2*)(sm + P_XL + off) = make_uint2(l0, l1);
        float4 wq4 = *(const float4*)(Wq + (size_t)r * 128 + cq * 4);
        split2(wq4.x, wq4.y, h0, l0);
        split2(wq4.z, wq4.w, h1, l1);
        *(uint2*)(sm + P_WQH + off) = make_uint2(h0, h1);
        *(uint2*)(sm + P_WQL + off) = make_uint2(l0, l1);
        float4 wu4 = *(const float4*)(Wu + (size_t)r * 128 + cq * 4);
        split2(wu4.x, wu4.y, h0, l0);
        split2(wu4.z, wu4.w, h1, l1);
        *(uint2*)(sm + P_WUH + off) = make_uint2(h0, h1);
        *(uint2*)(sm + P_WUL + off) = make_uint2(l0, l1);
    }
    if (tid < 128) wvs[tid] = wv[tid];
    __syncthreads();

    // gating scalars
    {
        float4 wv4 = ((const float4*)wvs)[lane];
        float bv0 = bv[0];
        for (int rr = 0; rr < 16; rr++) {
            int gr = row0 + 16 * w + rr;
            float4 xv = ((const float4*)(X + (size_t)gr * 128))[lane];
            float s = xv.x * wv4.x + xv.y * wv4.y + xv.z * wv4.z + xv.w * wv4.w;
#pragma unroll
            for (int o = 16; o; o >>= 1) s += __shfl_xor_sync(0xffffffffu, s, o);
            if (lane == 0) {
                float v = fmaxf(s + bv0, 0.f);
                Vs[gr]  = v;
                Vsm[gr] = v * mask[gr];
            }
        }
    }

    const uint32_t a_row  = 16 * w + (lane & 15);
    const uint32_t a_cadd = (lane & 16) ? 16 : 0;
    const uint32_t u_radd = (uint32_t)(lane & 15);
    const uint32_t u_cadd = (lane & 16) ? 16 : 0;
    const int r0 = 16 * w + (lane >> 2), r1 = r0 + 8;

    for (int g = 0; g < 2; g++) {
        const uint32_t WH = g ? P_WUH : P_WQH;
        const uint32_t WL = g ? P_WUL : P_WQL;
        float acc[16][4];
#pragma unroll
        for (int n = 0; n < 16; n++)
#pragma unroll
            for (int c = 0; c < 4; c++) acc[n][c] = 0.f;

#pragma unroll
        for (int kt = 0; kt < 8; kt++) {
            uint32_t aoff = a_row * IROWB + kt * 32 + a_cadd;
            uint32_t ah[4], al[4];
            ldsm_x4(ah, sb + P_XH + aoff);
            ldsm_x4(al, sb + P_XL + aoff);
#pragma unroll
            for (int np = 0; np < 8; np++) {
                uint32_t boff = (16 * kt + u_radd) * IROWB + np * 32 + u_cadd;
                uint32_t bh[4], bl[4];
                ldsm_x4t(bh, sb + WH + boff);
                ldsm_x4t(bl, sb + WL + boff);
                mma_bf16(acc[2*np],   ah, bh[0], bh[1]);
                mma_bf16(acc[2*np],   ah, bl[0], bl[1]);
                mma_bf16(acc[2*np],   al, bh[0], bh[1]);
                mma_bf16(acc[2*np+1], ah, bh[2], bh[3]);
                mma_bf16(acc[2*np+1], ah, bl[2], bl[3]);
                mma_bf16(acc[2*np+1], al, bh[2], bh[3]);
            }
        }

        const float* bias = g ? bu : bq;
        __nv_bfloat16* Oh = g ? Uh : Qh;
        __nv_bfloat16* Ol = g ? Ul : Ql;
#pragma unroll
        for (int n = 0; n < 16; n++) {
            int d = 8 * n + 2 * (lane & 3);
            float2 bb = *(const float2*)(bias + d);
            float v00 = acc[n][0] + bb.x, v01 = acc[n][1] + bb.y;
            float v10 = acc[n][2] + bb.x, v11 = acc[n][3] + bb.y;
            if (g) {
                v00 = fmaxf(v00, 0.f); v01 = fmaxf(v01, 0.f);
                v10 = fmaxf(v10, 0.f); v11 = fmaxf(v11, 0.f);
            }
            uint32_t h, l;
            split2(v00, v01, h, l);
            *(uint32_t*)(Oh + (size_t)(row0 + r0) * 128 + d) = h;
            *(uint32_t*)(Ol + (size_t)(row0 + r0) * 128 + d) = l;
            split2(v10, v11, h, l);
            *(uint32_t*)(Oh + (size_t)(row0 + r1) * 128 + d) = h;
            *(uint32_t*)(Ol + (size_t)(row0 + r1) * 128 + d) = l;
        }
    }
}

// =====================================================================
// embed (mma): out = relu(A @ W + b), both sequences in one launch
// =====================================================================
__global__ __launch_bounds__(256) void embed_mma_kernel(
    const float* __restrict__ A1, const float* __restrict__ W1,
    const float* __restrict__ b1, float* __restrict__ out1,
    const float* __restrict__ A2, const float* __restrict__ W2,
    const float* __restrict__ b2, float* __restrict__ out2) {
    extern __shared__ __align__(16) char sm[];
    const int tid = threadIdx.x;
    const int w   = tid >> 5, lane = tid & 31;
    const int row0 = blockIdx.x * 128;
    const int z = blockIdx.y;
    const uint32_t sb = smem_u32(sm);

    const float* A = z ? A2 : A1;
    const float* W = z ? W2 : W1;
    const float* bias = z ? b2 : b1;
    float* out = z ? out2 : out1;

    for (int idx = tid; idx < 128 * 32; idx += 256) {
        int r = idx >> 5, cq = idx & 31;
        uint32_t off = (uint32_t)(r * IROWB + cq * 8);
        uint32_t h0, l0, h1, l1;
        float4 av = *(const float4*)(A + (size_t)(row0 + r) * 128 + cq * 4);
        split2(av.x, av.y, h0, l0);
        split2(av.z, av.w, h1, l1);
        *(uint2*)(sm + E_XH + off) = make_uint2(h0, h1);
        *(uint2*)(sm + E_XL + off) = make_uint2(l0, l1);
        float4 wv4 = *(const float4*)(W + (size_t)r * 128 + cq * 4);
        split2(wv4.x, wv4.y, h0, l0);
        split2(wv4.z, wv4.w, h1, l1);
        *(uint2*)(sm + E_WH + off) = make_uint2(h0, h1);
        *(uint2*)(sm + E_WL + off) = make_uint2(l0, l1);
    }
    __syncthreads();

    const uint32_t a_row  = 16 * w + (lane & 15);
    const uint32_t a_cadd = (lane & 16) ? 16 : 0;
    const uint32_t u_radd = (uint32_t)(lane & 15);
    const uint32_t u_cadd = (lane & 16) ? 16 : 0;
    const int r0 = 16 * w + (lane >> 2), r1 = r0 + 8;

    float acc[16][4];
#pragma unroll
    for (int n = 0; n < 16; n++)
#pragma unroll
        for (int c = 0; c < 4; c++) acc[n][c] = 0.f;

#pragma unroll
    for (int kt = 0; kt < 8; kt++) {
        uint32_t aoff = a_row * IROWB + kt * 32 + a_cadd;
        uint32_t ah[4], al[4];
        ldsm_x4(ah, sb + E_XH + aoff);
        ldsm_x4(al, sb + E_XL + aoff);
#pragma unroll
        for (int np = 0; np < 8; np++) {
            uint32_t boff = (16 * kt + u_radd) * IROWB + np * 32 + u_cadd;
            uint32_t bh[4], bl[4];
            ldsm_x4t(bh, sb + E_WH + boff);
            ldsm_x4t(bl, sb + E_WL + boff);
            mma_bf16(acc[2*np],   ah, bh[0], bh[1]);
            mma_bf16(acc[2*np],   ah, bl[0], bl[1]);
            mma_bf16(acc[2*np],   al, bh[0], bh[1]);
            mma_bf16(acc[2*np+1], ah, bh[2], bh[3]);
            mma_bf16(acc[2*np+1], ah, bl[2], bl[3]);
            mma_bf16(acc[2*np+1], al, bh[2], bh[3]);
        }
    }

#pragma unroll
    for (int n = 0; n < 16; n++) {
        int d = 8 * n + 2 * (lane & 3);
        float2 bb = *(const float2*)(bias + d);
        float2 o0, o1;
        o0.x = fmaxf(acc[n][0] + bb.x, 0.f);
        o0.y = fmaxf(acc[n][1] + bb.y, 0.f);
        o1.x = fmaxf(acc[n][2] + bb.x, 0.f);
        o1.y = fmaxf(acc[n][3] + bb.y, 0.f);
        *(float2*)(out + (size_t)(row0 + r0) * 128 + d) = o0;
        *(float2*)(out + (size_t)(row0 + r1) * 128 + d) = o1;
    }
}

// ---------------- layernorm, both tensors in one launch ----------------
__global__ __launch_bounds__(256) void ln2_kernel(
    float* __restrict__ X, float* __restrict__ Y,
    const float* __restrict__ g1, const float* __restrict__ b1,
    const float* __restrict__ g2, const float* __restrict__ b2) {
    int blk = blockIdx.x;
    float* T; const float* g; const float* bb;
    if (blk < 2048) { T = X; g = g1; bb = b1; }
    else            { T = Y; g = g2; bb = b2; blk -= 2048; }
    int row  = blk * 8 + (threadIdx.x >> 5);
    int lane = threadIdx.x & 31;
    float4* Xr = (float4*)(T + (size_t)row * 128);
    float4 v = Xr[lane];
    float s = v.x + v.y + v.z + v.w;
#pragma unroll
    for (int o = 16; o; o >>= 1) s += __shfl_xor_sync(0xffffffffu, s, o);
    float m = s * (1.f/128.f);
    float d0 = v.x - m, d1 = v.y - m, d2 = v.z - m, d3 = v.w - m;
    float q = d0*d0 + d1*d1 + d2*d2 + d3*d3;
#pragma unroll
    for (int o = 16; o; o >>= 1) q += __shfl_xor_sync(0xffffffffu, q, o);
    float inv = rsqrtf(q * (1.f/128.f) + 1e-5f);
    float4 gg = ((const float4*)g)[lane];
    float4 bv = ((const float4*)bb)[lane];
    v.x = d0*inv*gg.x + bv.x;
    v.y = d1*inv*gg.y + bv.y;
    v.z = d2*inv*gg.z + bv.z;
    v.w = d3*inv*gg.w + bv.w;
    Xr[lane] = v;
}

__device__ __forceinline__ float blk_reduce(float v, float* red, bool ismax) {
#pragma unroll
    for (int o = 16; o; o >>= 1) {
        float t = __shfl_xor_sync(0xffffffffu, v, o);
        v = ismax ? fmaxf(v, t) : v + t;
    }
    if ((threadIdx.x & 31) == 0) red[threadIdx.x >> 5] = v;
    __syncthreads();
    float r = red[0];
#pragma unroll
    for (int i = 1; i < 8; i++) r = ismax ? fmaxf(r, red[i]) : r + red[i];
    __syncthreads();
    return r;
}

__global__ __launch_bounds__(256) void pool_head_kernel(
    const float* __restrict__ Xg, const float* __restrict__ Yg,
    const float* __restrict__ fc_w, const float* __restrict__ fc_b,
    const float* __restrict__ out_w, const float* __restrict__ out_b,
    float* __restrict__ out) {
    __shared__ float w[1024];
    __shared__ float red[8];
    __shared__ float pp[256];
    __shared__ float xp[128];
    __shared__ float yp[128];
    const int tid = threadIdx.x;
    const int b   = blockIdx.x;

    for (int s = 0; s < 2; s++) {
        const float* S = (s ? Yg : Xg) + (size_t)b * SEQL * 128;
        float* dst = s ? yp : xp;
        for (int l = tid; l < SEQL; l += 256) {
            const float4* row = (const float4*)(S + (size_t)l*128);
            float acc = 0.f;
#pragma unroll
            for (int c = 0; c < 32; c++) {
                float4 v = row[c];
                acc += v.x*v.x + v.y*v.y + v.z*v.z + v.w*v.w;
            }
            w[l] = sqrtf(acc);
        }
        __syncthreads();
        float lm = -1e30f;
        for (int l = tid; l < SEQL; l += 256) lm = fmaxf(lm, w[l]);
        float mx = blk_reduce(lm, red, true);
        float ls = 0.f;
        for (int l = tid; l < SEQL; l += 256) { float e = expf(w[l] - mx); w[l] = e; ls += e; }
        float tot = blk_reduce(ls, red, false);
        float inv = 1.f / tot;

        int d = tid & 127, halfi = tid >> 7;
        float p = 0.f;
        for (int l = halfi; l < SEQL; l += 2) p += S[(size_t)l*128 + d] * w[l];
        pp[halfi*128 + d] = p;
        __syncthreads();
        if (tid < 128) dst[tid] = (pp[tid] + pp[128 + tid]) * inv;
        __syncthreads();
    }

    float h = 0.f;
    if (tid < 128) {
        h = fc_b[tid];
        for (int k2 = 0; k2 < 128; k2++) h += xp[k2] * fc_w[k2*128 + tid];
        for (int k2 = 0; k2 < 128; k2++) h += yp[k2] * fc_w[(128 + k2)*128 + tid];
        h = fmaxf(h, 0.f) * out_w[tid];
    }
    float tot = blk_reduce(h, red, false);
    if (tid == 0) out[b] = 1.f / (1.f + expf(-(tot + out_b[0])));
}

// ---------------- launch ----------------
extern "C" void kernel_launch(void* const* d_in, const int* in_sizes, int n_in,
                              void* d_out, int out_size) {
    (void)in_sizes; (void)n_in; (void)out_size;
    const float* seq1  = (const float*)d_in[0];
    const float* seq2  = (const float*)d_in[1];
    const float* mask1 = (const float*)d_in[2];
    const float* mask2 = (const float*)d_in[3];
    const float* l1_w  = (const float*)d_in[4];
    const float* l1_b  = (const float*)d_in[5];
    const float* l2_w  = (const float*)d_in[6];
    const float* l2_b  = (const float*)d_in[7];
    const float* ln1_g = (const float*)d_in[8];
    const float* ln1_b = (const float*)d_in[9];
    const float* ln2_g = (const float*)d_in[10];
    const float* ln2_b = (const float*)d_in[11];
    const float* wq_w  = (const float*)d_in[12];
    const float* wq_b  = (const float*)d_in[13];
    const float* wk_w  = (const float*)d_in[14];
    const float* wk_b  = (const float*)d_in[15];
    const float* wvx_w = (const float*)d_in[16];
    const float* wvx_b = (const float*)d_in[17];
    const float* wvy_w = (const float*)d_in[18];
    const float* wvy_b = (const float*)d_in[19];
    const float* wx_w  = (const float*)d_in[20];
    const float* wx_b  = (const float*)d_in[21];
    const float* wy_w  = (const float*)d_in[22];
    const float* wy_b  = (const float*)d_in[23];
    const float* fc_w  = (const float*)d_in[24];
    const float* fc_b  = (const float*)d_in[25];
    const float* out_w = (const float*)d_in[26];
    const float* out_b = (const float*)d_in[27];

    float *x, *y, *vx, *vy, *vxm, *vym;
    __nv_bfloat16 *qh, *ql, *kh, *kl, *xuh, *xul, *yuh, *yul;
    cudaGetSymbolAddress((void**)&x,   g_x);
    cudaGetSymbolAddress((void**)&y,   g_y);
    cudaGetSymbolAddress((void**)&qh,  g_qh);
    cudaGetSymbolAddress((void**)&ql,  g_ql);
    cudaGetSymbolAddress((void**)&kh,  g_kh);
    cudaGetSymbolAddress((void**)&kl,  g_kl);
    cudaGetSymbolAddress((void**)&xuh, g_xuh);
    cudaGetSymbolAddress((void**)&xul, g_xul);
    cudaGetSymbolAddress((void**)&yuh, g_yuh);
    cudaGetSymbolAddress((void**)&yul, g_yul);
    cudaGetSymbolAddress((void**)&vx,  g_vx);
    cudaGetSymbolAddress((void**)&vy,  g_vy);
    cudaGetSymbolAddress((void**)&vxm, g_vxm);
    cudaGetSymbolAddress((void**)&vym, g_vym);

    cudaFuncSetAttribute(embed_mma_kernel,    cudaFuncAttributeMaxDynamicSharedMemorySize, E_SMEM);
    cudaFuncSetAttribute(proj_mma_kernel,     cudaFuncAttributeMaxDynamicSharedMemorySize, P_SMEM);
    cudaFuncSetAttribute(interact_mma_kernel, cudaFuncAttributeMaxDynamicSharedMemorySize, I_SMEM);

    embed_mma_kernel<<<dim3(128, 2), 256, E_SMEM>>>(seq1, l1_w, l1_b, x,
                                                    seq2, l2_w, l2_b, y);

    for (int i = 0; i < 3; i++) {
        ln2_kernel<<<4096, 256>>>(x, y, ln1_g + i*128, ln1_b + i*128,
                                  ln2_g + i*128, ln2_b + i*128);
        proj_mma_kernel<<<dim3(128, 2), 256, P_SMEM>>>(
            x, y,
            wq_w + i*16384, wq_b + i*128, wx_w + i*16384, wx_b + i*128,
            wvx_w + i*128, wvx_b + i,
            wk_w + i*16384, wk_b + i*128, wy_w + i*16384, wy_b + i*128,
            wvy_w + i*128, wvy_b + i,
            mask1, mask2,
            qh, ql, xuh, xul, kh, kl, yuh, yul,
            vx, vxm, vy, vym);
        interact_mma_kernel<<<dim3(8, 16, 2), 256, I_SMEM>>>(
            qh, ql, kh, kl, xuh, xul, yuh, yul, vxm, vy, vym, vx, x, y);
    }
    pool_head_kernel<<<16, 256>>>(x, y, fc_w, fc_b, out_w, out_b, (float*)d_out);
}

// round 7
// speedup vs baseline: 3.1512x; 1.0063x over previous
#include <cuda_runtime.h>
#include <cuda_bf16.h>
#include <cstdint>
#include <math.h>

#define NROWS 16384        // B * L = 16 * 1024
#define SEQL  1024
#define SCALE_INV 0.08838834764831845f   // 1/sqrt(128)

// ---------------- persistent scratch ----------------
__device__ float g_x [NROWS*128];
__device__ float g_y [NROWS*128];
__device__ __nv_bfloat16 g_qh [NROWS*128];
__device__ __nv_bfloat16 g_ql [NROWS*128];
__device__ __nv_bfloat16 g_kh [NROWS*128];
__device__ __nv_bfloat16 g_kl [NROWS*128];
__device__ __nv_bfloat16 g_xuh[NROWS*128];
__device__ __nv_bfloat16 g_xul[NROWS*128];
__device__ __nv_bfloat16 g_yuh[NROWS*128];
__device__ __nv_bfloat16 g_yul[NROWS*128];
__device__ float g_vx [NROWS];
__device__ float g_vy [NROWS];
__device__ float g_vxm[NROWS];
__device__ float g_vym[NROWS];

__device__ __forceinline__ float sigmoidf_fast(float x) {
    return __fdividef(1.f, 1.f + __expf(-x));
}

__device__ __forceinline__ uint32_t smem_u32(const void* p) {
    uint32_t a;
    asm("{ .reg .u64 t; cvta.to.shared.u64 t, %1; cvt.u32.u64 %0, t; }" : "=r"(a) : "l"(p));
    return a;
}

__device__ __forceinline__ uint32_t packbf(__nv_bfloat16 a, __nv_bfloat16 b) {
    __nv_bfloat162 t(a, b);
    return *reinterpret_cast<uint32_t*>(&t);
}

__device__ __forceinline__ void split2(float a, float b, uint32_t& hi, uint32_t& lo) {
    __nv_bfloat16 h0 = __float2bfloat16_rn(a), h1 = __float2bfloat16_rn(b);
    hi = packbf(h0, h1);
    lo = packbf(__float2bfloat16_rn(a - __bfloat162float(h0)),
                __float2bfloat16_rn(b - __bfloat162float(h1)));
}

__device__ __forceinline__ void ldsm_x4(uint32_t r[4], uint32_t addr) {
    asm volatile("ldmatrix.sync.aligned.m8n8.x4.shared.b16 {%0,%1,%2,%3}, [%4];"
                 : "=r"(r[0]), "=r"(r[1]), "=r"(r[2]), "=r"(r[3]) : "r"(addr));
}
__device__ __forceinline__ void ldsm_x4t(uint32_t r[4], uint32_t addr) {
    asm volatile("ldmatrix.sync.aligned.m8n8.x4.trans.shared.b16 {%0,%1,%2,%3}, [%4];"
                 : "=r"(r[0]), "=r"(r[1]), "=r"(r[2]), "=r"(r[3]) : "r"(addr));
}
__device__ __forceinline__ void mma_bf16(float c[4], const uint32_t a[4],
                                         uint32_t b0, uint32_t b1) {
    asm volatile(
        "mma.sync.aligned.m16n8k16.row.col.f32.bf16.bf16.f32 "
        "{%0,%1,%2,%3}, {%4,%5,%6,%7}, {%8,%9}, {%0,%1,%2,%3};"
        : "+f"(c[0]), "+f"(c[1]), "+f"(c[2]), "+f"(c[3])
        : "r"(a[0]), "r"(a[1]), "r"(a[2]), "r"(a[3]), "r"(b0), "r"(b1));
}

__device__ __forceinline__ void cp16(uint32_t saddr, const void* g) {
    asm volatile("cp.async.cg.shared.global [%0], [%1], 16;" :: "r"(saddr), "l"(g));
}
__device__ __forceinline__ void cp_commit() {
    asm volatile("cp.async.commit_group;" ::: "memory");
}
template<int N>
__device__ __forceinline__ void cp_wait() {
    asm volatile("cp.async.wait_group %0;" :: "n"(N) : "memory");
}

// ---- smem geometry ----
#define IROWB 272
#define QTILE (128 * IROWB)      // 34816
#define STILE (64 * IROWB)       // 17408
#define JTILE (32 * IROWB)       // 8704

// interact smem (128-thread CTA, 64 i-rows, 32-row j-tiles; 2 CTAs/SM)
#define O_QH  0
#define O_QL  STILE
#define O_ST  (2 * STILE)        // 34816
#define S_KH  0
#define S_KL  JTILE
#define S_UH  (2 * JTILE)
#define S_UL  (3 * JTILE)
#define S_BS  (4 * JTILE)        // 32 floats
#define STAGE (4 * JTILE + 256)  // 35072
#define O_AS  (O_ST + 2 * STAGE) // 104960
#define I_SMEM (O_AS + 256)      // 105216

// proj smem
#define P_XH  0
#define P_XL  QTILE
#define P_WQH (2 * QTILE)
#define P_WQL (3 * QTILE)
#define P_WUH (4 * QTILE)
#define P_WUL (5 * QTILE)
#define P_WV  (6 * QTILE)
#define P_SMEM (P_WV + 512)      // 209408

// embed smem
#define E_XH  0
#define E_XL  QTILE
#define E_WH  (2 * QTILE)
#define E_WL  (3 * QTILE)
#define E_SMEM (4 * QTILE)       // 139264

// =====================================================================
// interact: 128 threads / 4 warps, 64 i-rows per CTA, 32-row j-tiles.
// blockIdx.z selects x-pass / y-pass.
// =====================================================================
__global__ __launch_bounds__(128, 2) void interact_mma_kernel(
    const __nv_bfloat16* __restrict__ qh, const __nv_bfloat16* __restrict__ ql,
    const __nv_bfloat16* __restrict__ kh, const __nv_bfloat16* __restrict__ kl,
    const __nv_bfloat16* __restrict__ xuh, const __nv_bfloat16* __restrict__ xul,
    const __nv_bfloat16* __restrict__ yuh, const __nv_bfloat16* __restrict__ yul,
    const float* __restrict__ vxm, const float* __restrict__ vy,
    const float* __restrict__ vym, const float* __restrict__ vx,
    float* __restrict__ xO, float* __restrict__ yO) {
    extern __shared__ __align__(16) char sm[];
    const int tid  = threadIdx.x;
    const int w    = tid >> 5, lane = tid & 31;
    const int b    = blockIdx.y;
    const int i0   = blockIdx.x * 64;
    const int z    = blockIdx.z;
    const uint32_t sb = smem_u32(sm);
    float* aSs = (float*)(sm + O_AS);

    const __nv_bfloat16* Ah = z ? kh  : qh;
    const __nv_bfloat16* Al = z ? kl  : ql;
    const __nv_bfloat16* Kh = z ? qh  : kh;
    const __nv_bfloat16* Kl = z ? ql  : kl;
    const __nv_bfloat16* Uh = z ? xuh : yuh;
    const __nv_bfloat16* Ul = z ? xul : yul;
    const float* aS = z ? vym : vxm;
    const float* bS = z ? vx  : vy;
    float* Out      = z ? yO  : xO;

    const size_t rowbase = (size_t)(b * SEQL + i0) * 128;

    // A tile: 64 rows hi/lo + aS
    for (int i = tid; i < 64 * 16; i += 128) {
        int r = i >> 4, c = i & 15;
        uint32_t ro = (uint32_t)(r * IROWB + c * 16);
        size_t go = rowbase + (size_t)r * 128 + c * 8;
        cp16(sb + O_QH + ro, Ah + go);
        cp16(sb + O_QL + ro, Al + go);
    }
    if (tid < 16) cp16(sb + O_AS + tid * 16, aS + b * SEQL + i0 + tid * 4);

#define ISSUE_STAGE(JT, BUF) do { \
        const size_t jb = (size_t)(b * SEQL + (JT) * 32) * 128; \
        uint32_t st = sb + O_ST + (BUF) * STAGE; \
        for (int i = tid; i < 32 * 16; i += 128) { \
            int r = i >> 4, c = i & 15; \
            uint32_t ro = (uint32_t)(r * IROWB + c * 16); \
            size_t go = jb + (size_t)r * 128 + c * 8; \
            cp16(st + S_KH + ro, Kh + go); \
            cp16(st + S_KL + ro, Kl + go); \
            cp16(st + S_UH + ro, Uh + go); \
            cp16(st + S_UL + ro, Ul + go); \
        } \
        if (tid < 8) cp16(st + S_BS + tid * 16, bS + b * SEQL + (JT) * 32 + tid * 4); \
    } while (0)

    ISSUE_STAGE(0, 0);
    cp_commit();

    float oacc[16][4];
#pragma unroll
    for (int n = 0; n < 16; n++)
#pragma unroll
        for (int c = 0; c < 4; c++) oacc[n][c] = 0.f;

    const uint32_t a_row  = 16 * w + (lane & 15);
    const uint32_t a_cadd = (lane & 16) ? 16 : 0;
    const uint32_t b_rsub = (uint32_t)(((lane & 16) ? 8 : 0) + (lane & 7));
    const uint32_t b_cadd = (lane & 8) ? 16 : 0;
    const uint32_t u_radd = (uint32_t)(lane & 15);
    const uint32_t u_cadd = (lane & 16) ? 16 : 0;

    for (int jt = 0; jt < 32; jt++) {
        if (jt + 1 < 32) {
            ISSUE_STAGE(jt + 1, (jt + 1) & 1);
            cp_commit();
            cp_wait<1>();
        } else {
            cp_wait<0>();
        }
        __syncthreads();

        const uint32_t st = sb + O_ST + (jt & 1) * STAGE;
        const float* bSs = (const float*)(sm + O_ST + (jt & 1) * STAGE + S_BS);

        // ---- GEMM1: S[16 x 32] = Q_w @ K^T over d=128 ----
        float sacc[4][4];
#pragma unroll
        for (int n = 0; n < 4; n++)
#pragma unroll
            for (int c = 0; c < 4; c++) sacc[n][c] = 0.f;

#pragma unroll
        for (int kt = 0; kt < 8; kt++) {
            uint32_t aoff = a_row * IROWB + kt * 32 + a_cadd;
            uint32_t ah[4], al[4];
            ldsm_x4(ah, sb + O_QH + aoff);
            ldsm_x4(al, sb + O_QL + aoff);
#pragma unroll
            for (int np = 0; np < 2; np++) {
                uint32_t boff = (16 * np + b_rsub) * IROWB + kt * 32 + b_cadd;
                uint32_t bh[4], bl[4];
                ldsm_x4(bh, st + S_KH + boff);
                ldsm_x4(bl, st + S_KL + boff);
                mma_bf16(sacc[2*np],   ah, bh[0], bh[1]);
                mma_bf16(sacc[2*np],   ah, bl[0], bl[1]);
                mma_bf16(sacc[2*np],   al, bh[0], bh[1]);
                mma_bf16(sacc[2*np+1], ah, bh[2], bh[3]);
                mma_bf16(sacc[2*np+1], ah, bl[2], bl[3]);
                mma_bf16(sacc[2*np+1], al, bh[2], bh[3]);
            }
        }

        // ---- P = sigmoid(S/sqrt(D)) * bS_j, split hi/lo in regs ----
        uint32_t ph[4][2], pl[4][2];
#pragma unroll
        for (int n = 0; n < 4; n++) {
            int j0 = 8 * n + 2 * (lane & 3);
            float2 bv = *(const float2*)(bSs + j0);
            float p00 = sigmoidf_fast(sacc[n][0] * SCALE_INV) * bv.x;
            float p01 = sigmoidf_fast(sacc[n][1] * SCALE_INV) * bv.y;
            float p10 = sigmoidf_fast(sacc[n][2] * SCALE_INV) * bv.x;
            float p11 = sigmoidf_fast(sacc[n][3] * SCALE_INV) * bv.y;
            split2(p00, p01, ph[n][0], pl[n][0]);
            split2(p10, p11, ph[n][1], pl[n][1]);
        }

        // ---- GEMM2: O[16 x 128] += P[16 x 32] @ U[32 x 128] ----
#pragma unroll
        for (int kt = 0; kt < 2; kt++) {
            uint32_t ah[4] = { ph[2*kt][0], ph[2*kt][1], ph[2*kt+1][0], ph[2*kt+1][1] };
            uint32_t al[4] = { pl[2*kt][0], pl[2*kt][1], pl[2*kt+1][0], pl[2*kt+1][1] };
#pragma unroll
            for (int np = 0; np < 8; np++) {
                uint32_t uoff = (16 * kt + u_radd) * IROWB + np * 32 + u_cadd;
                uint32_t uh[4], ul[4];
                ldsm_x4t(uh, st + S_UH + uoff);
                ldsm_x4t(ul, st + S_UL + uoff);
                mma_bf16(oacc[2*np],   ah, uh[0], uh[1]);
                mma_bf16(oacc[2*np],   ah, ul[0], ul[1]);
                mma_bf16(oacc[2*np],   al, uh[0], uh[1]);
                mma_bf16(oacc[2*np+1], ah, uh[2], uh[3]);
                mma_bf16(oacc[2*np+1], ah, ul[2], ul[3]);
                mma_bf16(oacc[2*np+1], al, uh[2], uh[3]);
            }
        }
        __syncthreads();
    }
#undef ISSUE_STAGE

    {
        int r0 = 16 * w + (lane >> 2), r1 = r0 + 8;
        float av0 = aSs[r0], av1 = aSs[r1];
        float* Ob = Out + rowbase;
#pragma unroll
        for (int n = 0; n < 16; n++) {
            int d = 8 * n + 2 * (lane & 3);
            float2 o0 = *(float2*)(Ob + (size_t)r0 * 128 + d);
            o0.x += av0 * oacc[n][0];
            o0.y += av0 * oacc[n][1];
            *(float2*)(Ob + (size_t)r0 * 128 + d) = o0;
            float2 o1 = *(float2*)(Ob + (size_t)r1 * 128 + d);
            o1.x += av1 * oacc[n][2];
            o1.y += av1 * oacc[n][3];
            *(float2*)(Ob + (size_t)r1 * 128 + d) = o1;
        }
    }
}

// =====================================================================
// proj (mma), both sides in one launch (blockIdx.y selects)
// =====================================================================
__global__ __launch_bounds__(256) void proj_mma_kernel(
    const float* __restrict__ X1, const float* __restrict__ X2,
    const float* __restrict__ Wq1, const float* __restrict__ bq1,
    const float* __restrict__ Wu1, const float* __restrict__ bu1,
    const float* __restrict__ wv1, const float* __restrict__ bv1,
    const float* __restrict__ Wq2, const float* __restrict__ bq2,
    const float* __restrict__ Wu2, const float* __restrict__ bu2,
    const float* __restrict__ wv2, const float* __restrict__ bv2,
    const float* __restrict__ mask1, const float* __restrict__ mask2,
    __nv_bfloat16* __restrict__ qh, __nv_bfloat16* __restrict__ ql,
    __nv_bfloat16* __restrict__ xuh, __nv_bfloat16* __restrict__ xul,
    __nv_bfloat16* __restrict__ kh, __nv_bfloat16* __restrict__ kl,
    __nv_bfloat16* __restrict__ yuh, __nv_bfloat16* __restrict__ yul,
    float* __restrict__ vx, float* __restrict__ vxm,
    float* __restrict__ vy, float* __restrict__ vym) {
    extern __shared__ __align__(16) char sm[];
    const int tid = threadIdx.x;
    const int w   = tid >> 5, lane = tid & 31;
    const int row0 = blockIdx.x * 128;
    const int z = blockIdx.y;
    const uint32_t sb = smem_u32(sm);
    float* wvs = (float*)(sm + P_WV);

    const float* X  = z ? X2 : X1;
    const float* Wq = z ? Wq2 : Wq1;
    const float* bq = z ? bq2 : bq1;
    const float* Wu = z ? Wu2 : Wu1;
    const float* bu = z ? bu2 : bu1;
    const float* wv = z ? wv2 : wv1;
    const float* bv = z ? bv2 : bv1;
    const float* mask = z ? mask2 : mask1;
    __nv_bfloat16* Qh = z ? kh : qh;
    __nv_bfloat16* Ql = z ? kl : ql;
    __nv_bfloat16* Uh = z ? yuh : xuh;
    __nv_bfloat16* Ul = z ? yul : xul;
    float* Vs  = z ? vy : vx;
    float* Vsm = z ? vym : vxm;

    for (int idx = tid; idx < 128 * 32; idx += 256) {
        int r = idx >> 5, cq = idx & 31;
        uint32_t off = (uint32_t)(r * IROWB + cq * 8);
        uint32_t h0, l0, h1, l1;
        float4 xv = *(const float4*)(X + (size_t)(row0 + r) * 128 + cq * 4);
        split2(xv.x, xv.y, h0, l0);
        split2(xv.z, xv.w, h1, l1);
        *(uint2*)(sm + P_XH + off) = make_uint2(h0, h1);
        *(uint2*)(sm + P_XL + off) = make_uint2(l0, l1);
        float4 wq4 = *(const float4*)(Wq + (size_t)r * 128 + cq * 4);
        split2(wq4.x, wq4.y, h0, l0);
        split2(wq4.z, wq4.w, h1, l1);
        *(uint2*)(sm + P_WQH + off) = make_uint2(h0, h1);
        *(uint2*)(sm + P_WQL + off) = make_uint2(l0, l1);
        float4 wu4 = *(const float4*)(Wu + (size_t)r * 128 + cq * 4);
        split2(wu4.x, wu4.y, h0, l0);
        split2(wu4.z, wu4.w, h1, l1);
        *(uint2*)(sm + P_WUH + off) = make_uint2(h0, h1);
        *(uint2*)(sm + P_WUL + off) = make_uint2(l0, l1);
    }
    if (tid < 128) wvs[tid] = wv[tid];
    __syncthreads();

    {
        float4 wv4 = ((const float4*)wvs)[lane];
        float bv0 = bv[0];
        for (int rr = 0; rr < 16; rr++) {
            int gr = row0 + 16 * w + rr;
            float4 xv = ((const float4*)(X + (size_t)gr * 128))[lane];
            float s = xv.x * wv4.x + xv.y * wv4.y + xv.z * wv4.z + xv.w * wv4.w;
#pragma unroll
            for (int o = 16; o; o >>= 1) s += __shfl_xor_sync(0xffffffffu, s, o);
            if (lane == 0) {
                float v = fmaxf(s + bv0, 0.f);
                Vs[gr]  = v;
                Vsm[gr] = v * mask[gr];
            }
        }
    }

    const uint32_t a_row  = 16 * w + (lane & 15);
    const uint32_t a_cadd = (lane & 16) ? 16 : 0;
    const uint32_t u_radd = (uint32_t)(lane & 15);
    const uint32_t u_cadd = (lane & 16) ? 16 : 0;
    const int r0 = 16 * w + (lane >> 2), r1 = r0 + 8;

    for (int g = 0; g < 2; g++) {
        const uint32_t WH = g ? P_WUH : P_WQH;
        const uint32_t WL = g ? P_WUL : P_WQL;
        float acc[16][4];
#pragma unroll
        for (int n = 0; n < 16; n++)
#pragma unroll
            for (int c = 0; c < 4; c++) acc[n][c] = 0.f;

#pragma unroll
        for (int kt = 0; kt < 8; kt++) {
            uint32_t aoff = a_row * IROWB + kt * 32 + a_cadd;
            uint32_t ah[4], al[4];
            ldsm_x4(ah, sb + P_XH + aoff);
            ldsm_x4(al, sb + P_XL + aoff);
#pragma unroll
            for (int np = 0; np < 8; np++) {
                uint32_t boff = (16 * kt + u_radd) * IROWB + np * 32 + u_cadd;
                uint32_t bh[4], bl[4];
                ldsm_x4t(bh, sb + WH + boff);
                ldsm_x4t(bl, sb + WL + boff);
                mma_bf16(acc[2*np],   ah, bh[0], bh[1]);
                mma_bf16(acc[2*np],   ah, bl[0], bl[1]);
                mma_bf16(acc[2*np],   al, bh[0], bh[1]);
                mma_bf16(acc[2*np+1], ah, bh[2], bh[3]);
                mma_bf16(acc[2*np+1], ah, bl[2], bl[3]);
                mma_bf16(acc[2*np+1], al, bh[2], bh[3]);
            }
        }

        const float* bias = g ? bu : bq;
        __nv_bfloat16* Oh = g ? Uh : Qh;
        __nv_bfloat16* Ol = g ? Ul : Ql;
#pragma unroll
        for (int n = 0; n < 16; n++) {
            int d = 8 * n + 2 * (lane & 3);
            float2 bb = *(const float2*)(bias + d);
            float v00 = acc[n][0] + bb.x, v01 = acc[n][1] + bb.y;
            float v10 = acc[n][2] + bb.x, v11 = acc[n][3] + bb.y;
            if (g) {
                v00 = fmaxf(v00, 0.f); v01 = fmaxf(v01, 0.f);
                v10 = fmaxf(v10, 0.f); v11 = fmaxf(v11, 0.f);
            }
            uint32_t h, l;
            split2(v00, v01, h, l);
            *(uint32_t*)(Oh + (size_t)(row0 + r0) * 128 + d) = h;
            *(uint32_t*)(Ol + (size_t)(row0 + r0) * 128 + d) = l;
            split2(v10, v11, h, l);
            *(uint32_t*)(Oh + (size_t)(row0 + r1) * 128 + d) = h;
            *(uint32_t*)(Ol + (size_t)(row0 + r1) * 128 + d) = l;
        }
    }
}

// =====================================================================
// embed (mma): out = relu(A @ W + b), both sequences in one launch
// =====================================================================
__global__ __launch_bounds__(256) void embed_mma_kernel(
    const float* __restrict__ A1, const float* __restrict__ W1,
    const float* __restrict__ b1, float* __restrict__ out1,
    const float* __restrict__ A2, const float* __restrict__ W2,
    const float* __restrict__ b2, float* __restrict__ out2) {
    extern __shared__ __align__(16) char sm[];
    const int tid = threadIdx.x;
    const int w   = tid >> 5, lane = tid & 31;
    const int row0 = blockIdx.x * 128;
    const int z = blockIdx.y;
    const uint32_t sb = smem_u32(sm);

    const float* A = z ? A2 : A1;
    const float* W = z ? W2 : W1;
    const float* bias = z ? b2 : b1;
    float* out = z ? out2 : out1;

    for (int idx = tid; idx < 128 * 32; idx += 256) {
        int r = idx >> 5, cq = idx & 31;
        uint32_t off = (uint32_t)(r * IROWB + cq * 8);
        uint32_t h0, l0, h1, l1;
        float4 av = *(const float4*)(A + (size_t)(row0 + r) * 128 + cq * 4);
        split2(av.x, av.y, h0, l0);
        split2(av.z, av.w, h1, l1);
        *(uint2*)(sm + E_XH + off) = make_uint2(h0, h1);
        *(uint2*)(sm + E_XL + off) = make_uint2(l0, l1);
        float4 wv4 = *(const float4*)(W + (size_t)r * 128 + cq * 4);
        split2(wv4.x, wv4.y, h0, l0);
        split2(wv4.z, wv4.w, h1, l1);
        *(uint2*)(sm + E_WH + off) = make_uint2(h0, h1);
        *(uint2*)(sm + E_WL + off) = make_uint2(l0, l1);
    }
    __syncthreads();

    const uint32_t a_row  = 16 * w + (lane & 15);
    const uint32_t a_cadd = (lane & 16) ? 16 : 0;
    const uint32_t u_radd = (uint32_t)(lane & 15);
    const uint32_t u_cadd = (lane & 16) ? 16 : 0;
    const int r0 = 16 * w + (lane >> 2), r1 = r0 + 8;

    float acc[16][4];
#pragma unroll
    for (int n = 0; n < 16; n++)
#pragma unroll
        for (int c = 0; c < 4; c++) acc[n][c] = 0.f;

#pragma unroll
    for (int kt = 0; kt < 8; kt++) {
        uint32_t aoff = a_row * IROWB + kt * 32 + a_cadd;
        uint32_t ah[4], al[4];
        ldsm_x4(ah, sb + E_XH + aoff);
        ldsm_x4(al, sb + E_XL + aoff);
#pragma unroll
        for (int np = 0; np < 8; np++) {
            uint32_t boff = (16 * kt + u_radd) * IROWB + np * 32 + u_cadd;
            uint32_t bh[4], bl[4];
            ldsm_x4t(bh, sb + E_WH + boff);
            ldsm_x4t(bl, sb + E_WL + boff);
            mma_bf16(acc[2*np],   ah, bh[0], bh[1]);
            mma_bf16(acc[2*np],   ah, bl[0], bl[1]);
            mma_bf16(acc[2*np],   al, bh[0], bh[1]);
            mma_bf16(acc[2*np+1], ah, bh[2], bh[3]);
            mma_bf16(acc[2*np+1], ah, bl[2], bl[3]);
            mma_bf16(acc[2*np+1], al, bh[2], bh[3]);
        }
    }

#pragma unroll
    for (int n = 0; n < 16; n++) {
        int d = 8 * n + 2 * (lane & 3);
        float2 bb = *(const float2*)(bias + d);
        float2 o0, o1;
        o0.x = fmaxf(acc[n][0] + bb.x, 0.f);
        o0.y = fmaxf(acc[n][1] + bb.y, 0.f);
        o1.x = fmaxf(acc[n][2] + bb.x, 0.f);
        o1.y = fmaxf(acc[n][3] + bb.y, 0.f);
        *(float2*)(out + (size_t)(row0 + r0) * 128 + d) = o0;
        *(float2*)(out + (size_t)(row0 + r1) * 128 + d) = o1;
    }
}

// ---------------- layernorm, both tensors in one launch ----------------
__global__ __launch_bounds__(256) void ln2_kernel(
    float* __restrict__ X, float* __restrict__ Y,
    const float* __restrict__ g1, const float* __restrict__ b1,
    const float* __restrict__ g2, const float* __restrict__ b2) {
    int blk = blockIdx.x;
    float* T; const float* g; const float* bb;
    if (blk < 2048) { T = X; g = g1; bb = b1; }
    else            { T = Y; g = g2; bb = b2; blk -= 2048; }
    int row  = blk * 8 + (threadIdx.x >> 5);
    int lane = threadIdx.x & 31;
    float4* Xr = (float4*)(T + (size_t)row * 128);
    float4 v = Xr[lane];
    float s = v.x + v.y + v.z + v.w;
#pragma unroll
    for (int o = 16; o; o >>= 1) s += __shfl_xor_sync(0xffffffffu, s, o);
    float m = s * (1.f/128.f);
    float d0 = v.x - m, d1 = v.y - m, d2 = v.z - m, d3 = v.w - m;
    float q = d0*d0 + d1*d1 + d2*d2 + d3*d3;
#pragma unroll
    for (int o = 16; o; o >>= 1) q += __shfl_xor_sync(0xffffffffu, q, o);
    float inv = rsqrtf(q * (1.f/128.f) + 1e-5f);
    float4 gg = ((const float4*)g)[lane];
    float4 bv = ((const float4*)bb)[lane];
    v.x = d0*inv*gg.x + bv.x;
    v.y = d1*inv*gg.y + bv.y;
    v.z = d2*inv*gg.z + bv.z;
    v.w = d3*inv*gg.w + bv.w;
    Xr[lane] = v;
}

__device__ __forceinline__ float blk_reduce(float v, float* red, bool ismax) {
#pragma unroll
    for (int o = 16; o; o >>= 1) {
        float t = __shfl_xor_sync(0xffffffffu, v, o);
        v = ismax ? fmaxf(v, t) : v + t;
    }
    if ((threadIdx.x & 31) == 0) red[threadIdx.x >> 5] = v;
    __syncthreads();
    float r = red[0];
#pragma unroll
    for (int i = 1; i < 8; i++) r = ismax ? fmaxf(r, red[i]) : r + red[i];
    __syncthreads();
    return r;
}

__global__ __launch_bounds__(256) void pool_head_kernel(
    const float* __restrict__ Xg, const float* __restrict__ Yg,
    const float* __restrict__ fc_w, const float* __restrict__ fc_b,
    const float* __restrict__ out_w, const float* __restrict__ out_b,
    float* __restrict__ out) {
    __shared__ float w[1024];
    __shared__ float red[8];
    __shared__ float pp[256];
    __shared__ float xp[128];
    __shared__ float yp[128];
    const int tid = threadIdx.x;
    const int b   = blockIdx.x;

    for (int s = 0; s < 2; s++) {
        const float* S = (s ? Yg : Xg) + (size_t)b * SEQL * 128;
        float* dst = s ? yp : xp;
        for (int l = tid; l < SEQL; l += 256) {
            const float4* row = (const float4*)(S + (size_t)l*128);
            float acc = 0.f;
#pragma unroll
            for (int c = 0; c < 32; c++) {
                float4 v = row[c];
                acc += v.x*v.x + v.y*v.y + v.z*v.z + v.w*v.w;
            }
            w[l] = sqrtf(acc);
        }
        __syncthreads();
        float lm = -1e30f;
        for (int l = tid; l < SEQL; l += 256) lm = fmaxf(lm, w[l]);
        float mx = blk_reduce(lm, red, true);
        float ls = 0.f;
        for (int l = tid; l < SEQL; l += 256) { float e = expf(w[l] - mx); w[l] = e; ls += e; }
        float tot = blk_reduce(ls, red, false);
        float inv = 1.f / tot;

        int d = tid & 127, halfi = tid >> 7;
        float p = 0.f;
        for (int l = halfi; l < SEQL; l += 2) p += S[(size_t)l*128 + d] * w[l];
        pp[halfi*128 + d] = p;
        __syncthreads();
        if (tid < 128) dst[tid] = (pp[tid] + pp[128 + tid]) * inv;
        __syncthreads();
    }

    float h = 0.f;
    if (tid < 128) {
        h = fc_b[tid];
        for (int k2 = 0; k2 < 128; k2++) h += xp[k2] * fc_w[k2*128 + tid];
        for (int k2 = 0; k2 < 128; k2++) h += yp[k2] * fc_w[(128 + k2)*128 + tid];
        h = fmaxf(h, 0.f) * out_w[tid];
    }
    float tot = blk_reduce(h, red, false);
    if (tid == 0) out[b] = 1.f / (1.f + expf(-(tot + out_b[0])));
}

// ---------------- launch ----------------
extern "C" void kernel_launch(void* const* d_in, const int* in_sizes, int n_in,
                              void* d_out, int out_size) {
    (void)in_sizes; (void)n_in; (void)out_size;
    const float* seq1  = (const float*)d_in[0];
    const float* seq2  = (const float*)d_in[1];
    const float* mask1 = (const float*)d_in[2];
    const float* mask2 = (const float*)d_in[3];
    const float* l1_w  = (const float*)d_in[4];
    const float* l1_b  = (const float*)d_in[5];
    const float* l2_w  = (const float*)d_in[6];
    const float* l2_b  = (const float*)d_in[7];
    const float* ln1_g = (const float*)d_in[8];
    const float* ln1_b = (const float*)d_in[9];
    const float* ln2_g = (const float*)d_in[10];
    const float* ln2_b = (const float*)d_in[11];
    const float* wq_w  = (const float*)d_in[12];
    const float* wq_b  = (const float*)d_in[13];
    const float* wk_w  = (const float*)d_in[14];
    const float* wk_b  = (const float*)d_in[15];
    const float* wvx_w = (const float*)d_in[16];
    const float* wvx_b = (const float*)d_in[17];
    const float* wvy_w = (const float*)d_in[18];
    const float* wvy_b = (const float*)d_in[19];
    const float* wx_w  = (const float*)d_in[20];
    const float* wx_b  = (const float*)d_in[21];
    const float* wy_w  = (const float*)d_in[22];
    const float* wy_b  = (const float*)d_in[23];
    const float* fc_w  = (const float*)d_in[24];
    const float* fc_b  = (const float*)d_in[25];
    const float* out_w = (const float*)d_in[26];
    const float* out_b = (const float*)d_in[27];

    float *x, *y, *vx, *vy, *vxm, *vym;
    __nv_bfloat16 *qh, *ql, *kh, *kl, *xuh, *xul, *yuh, *yul;
    cudaGetSymbolAddress((void**)&x,   g_x);
    cudaGetSymbolAddress((void**)&y,   g_y);
    cudaGetSymbolAddress((void**)&qh,  g_qh);
    cudaGetSymbolAddress((void**)&ql,  g_ql);
    cudaGetSymbolAddress((void**)&kh,  g_kh);
    cudaGetSymbolAddress((void**)&kl,  g_kl);
    cudaGetSymbolAddress((void**)&xuh, g_xuh);
    cudaGetSymbolAddress((void**)&xul, g_xul);
    cudaGetSymbolAddress((void**)&yuh, g_yuh);
    cudaGetSymbolAddress((void**)&yul, g_yul);
    cudaGetSymbolAddress((void**)&vx,  g_vx);
    cudaGetSymbolAddress((void**)&vy,  g_vy);
    cudaGetSymbolAddress((void**)&vxm, g_vxm);
    cudaGetSymbolAddress((void**)&vym, g_vym);

    cudaFuncSetAttribute(embed_mma_kernel,    cudaFuncAttributeMaxDynamicSharedMemorySize, E_SMEM);
    cudaFuncSetAttribute(proj_mma_kernel,     cudaFuncAttributeMaxDynamicSharedMemorySize, P_SMEM);
    cudaFuncSetAttribute(interact_mma_kernel, cudaFuncAttributeMaxDynamicSharedMemorySize, I_SMEM);

    embed_mma_kernel<<<dim3(128, 2), 256, E_SMEM>>>(seq1, l1_w, l1_b, x,
                                                    seq2, l2_w, l2_b, y);

    for (int i = 0; i < 3; i++) {
        ln2_kernel<<<4096, 256>>>(x, y, ln1_g + i*128, ln1_b + i*128,
                                  ln2_g + i*128, ln2_b + i*128);
        proj_mma_kernel<<<dim3(128, 2), 256, P_SMEM>>>(
            x, y,
            wq_w + i*16384, wq_b + i*128, wx_w + i*16384, wx_b + i*128,
            wvx_w + i*128, wvx_b + i,
            wk_w + i*16384, wk_b + i*128, wy_w + i*16384, wy_b + i*128,
            wvy_w + i*128, wvy_b + i,
            mask1, mask2,
            qh, ql, xuh, xul, kh, kl, yuh, yul,
            vx, vxm, vy, vym);
        interact_mma_kernel<<<dim3(16, 16, 2), 128, I_SMEM>>>(
            qh, ql, kh, kl, xuh, xul, yuh, yul, vxm, vy, vym, vx, x, y);
    }
    pool_head_kernel<<<16, 256>>>(x, y, fc_w, fc_b, out_w, out_b, (float*)d_out);
}